// round 3
// baseline (speedup 1.0000x reference)
#include <cuda_runtime.h>
#include <cstdint>

#define B_   64
#define N_   1024
#define BN   65536
#define H_   128
#define S_   12
#define CSR_CAP 512

#define K0_REAL 387
#define K0_PAD  392
#define K1_     768
#define NGATE   512

// d_out layout: [output 65536][hs 2*BN*H][cs 2*BN*H][attw BN*S]
#define HS_OFF   65536
#define CS_OFF   (65536 + 2 * BN * H_)
#define ATT_OFF  (CS_OFF + 2 * BN * H_)

// ---------------- scratch (device globals; no allocation allowed) ----------
__device__ float g_feats[(size_t)BN * 768];     // reused by both layers
__device__ float g_gates[(size_t)BN * 512];
__device__ float g_energy[S_ * BN];
__device__ float g_dpw[S_ * BN];
__device__ int   g_csr_cnt[N_];
__device__ int   g_csr_col[(size_t)N_ * CSR_CAP];
__device__ float g_csr_val[(size_t)N_ * CSR_CAP];

__device__ __forceinline__ float sigmoidf_(float x) { return 1.f / (1.f + expf(-x)); }

// ---------------- CSR build (deterministic per-row sequential scan) --------
__global__ void build_csr_kernel(const float* __restrict__ sup) {
    int n = blockIdx.x * blockDim.x + threadIdx.x;
    if (n >= N_) return;
    int cnt = 0;
    const float* row = sup + (size_t)n * N_;
    for (int m = 0; m < N_; m++) {
        float v = row[m];
        if (v != 0.f) {
            if (cnt < CSR_CAP) {
                g_csr_col[n * CSR_CAP + cnt] = m;
                g_csr_val[n * CSR_CAP + cnt] = v;
            }
            cnt++;
        }
    }
    g_csr_cnt[n] = cnt < CSR_CAP ? cnt : CSR_CAP;
}

// ---------------- fill x0 for layer 0: [input(1), h0(128)], pad zeros ------
__global__ void fill_x0_l0_kernel(const float* __restrict__ inputs,
                                  const float* __restrict__ h0) {
    int t = blockIdx.x * blockDim.x + threadIdx.x;
    if (t >= BN * 129) return;
    int r = t / 129;
    int c = t - r * 129;
    float v = (c == 0) ? inputs[r] : h0[r * H_ + (c - 1)];
    g_feats[(size_t)r * K0_PAD + c] = v;
}

__global__ void zero_pad_l0_kernel() {
    int t = blockIdx.x * blockDim.x + threadIdx.x;
    if (t >= BN * (K0_PAD - K0_REAL)) return;
    int r = t / (K0_PAD - K0_REAL);
    int c = K0_REAL + (t - r * (K0_PAD - K0_REAL));
    g_feats[(size_t)r * K0_PAD + c] = 0.f;
}

// ---------------- fill x0 for layer 1: [h0_new(128), h1(128)] --------------
__global__ void fill_x0_l1_kernel(const float* __restrict__ h0new,
                                  const float* __restrict__ h1) {
    int t = blockIdx.x * blockDim.x + threadIdx.x;
    if (t >= BN * 256) return;
    int r = t >> 8;
    int c = t & 255;
    float v = (c < H_) ? h0new[r * H_ + c] : h1[r * H_ + (c - H_)];
    g_feats[(size_t)r * K1_ + c] = v;
}

// ---------------- sparse diffusion: y = S@x (optionally 2*S@x - prev) ------
__global__ void spmm_kernel(int ld, int srcCol, int dstCol, int prevCol, int D, int cheb) {
    __shared__ int   scol[CSR_CAP];
    __shared__ float sval[CSR_CAP];
    int n = blockIdx.x;
    int b = blockIdx.y;
    int cnt = g_csr_cnt[n];
    for (int i = threadIdx.x; i < cnt; i += blockDim.x) {
        scol[i] = g_csr_col[n * CSR_CAP + i];
        sval[i] = g_csr_val[n * CSR_CAP + i];
    }
    __syncthreads();
    size_t rbase = ((size_t)b * N_ + n) * ld;
    for (int d = threadIdx.x; d < D; d += blockDim.x) {
        float acc = 0.f;
        for (int i = 0; i < cnt; i++) {
            acc += sval[i] * g_feats[((size_t)b * N_ + scol[i]) * ld + srcCol + d];
        }
        float y = acc;
        if (cheb) y = 2.f * acc - g_feats[rbase + prevCol + d];
        g_feats[rbase + dstCol + d] = y;
    }
}

// ---------------- fp32 SGEMM: gates[M,512] = feats[M,Kpad]@W[Kreal,512]+b --
// BM=BN=128, BK=8, 256 threads, 8x8 per thread. M,Kpad multiples of tile.
__global__ __launch_bounds__(256) void sgemm_kernel(
    const float* __restrict__ W, const float* __restrict__ bias,
    int Kpad, int Kreal, int lda) {
    __shared__ float As[8][128];
    __shared__ float Bs[8][128];
    int tid = threadIdx.x;
    int tx = tid & 15;         // 0..15 -> col groups of 8
    int ty = tid >> 4;         // 0..15 -> row groups of 8
    int rowBase = blockIdx.y * 128;
    int colBase = blockIdx.x * 128;

    float acc[8][8];
#pragma unroll
    for (int i = 0; i < 8; i++)
#pragma unroll
        for (int j = 0; j < 8; j++) acc[i][j] = 0.f;

    for (int k0 = 0; k0 < Kpad; k0 += 8) {
#pragma unroll
        for (int l = 0; l < 4; l++) {
            int e = tid + l * 256;            // 0..1023
            int r = e >> 3, kk = e & 7;
            As[kk][r] = g_feats[(size_t)(rowBase + r) * lda + k0 + kk];
        }
#pragma unroll
        for (int l = 0; l < 4; l++) {
            int e = tid + l * 256;
            int kk = e >> 7, j = e & 127;
            int kg = k0 + kk;
            Bs[kk][j] = (kg < Kreal) ? W[(size_t)kg * NGATE + colBase + j] : 0.f;
        }
        __syncthreads();
#pragma unroll
        for (int kk = 0; kk < 8; kk++) {
            float ra[8], rb[8];
            float4 a0 = *reinterpret_cast<const float4*>(&As[kk][ty * 8]);
            float4 a1 = *reinterpret_cast<const float4*>(&As[kk][ty * 8 + 4]);
            float4 b0 = *reinterpret_cast<const float4*>(&Bs[kk][tx * 8]);
            float4 b1 = *reinterpret_cast<const float4*>(&Bs[kk][tx * 8 + 4]);
            ra[0]=a0.x; ra[1]=a0.y; ra[2]=a0.z; ra[3]=a0.w;
            ra[4]=a1.x; ra[5]=a1.y; ra[6]=a1.z; ra[7]=a1.w;
            rb[0]=b0.x; rb[1]=b0.y; rb[2]=b0.z; rb[3]=b0.w;
            rb[4]=b1.x; rb[5]=b1.y; rb[6]=b1.z; rb[7]=b1.w;
#pragma unroll
            for (int i = 0; i < 8; i++)
#pragma unroll
                for (int j = 0; j < 8; j++) acc[i][j] += ra[i] * rb[j];
        }
        __syncthreads();
    }
#pragma unroll
    for (int i = 0; i < 8; i++) {
        int row = rowBase + ty * 8 + i;
#pragma unroll
        for (int j = 0; j < 8; j++) {
            int col = colBase + tx * 8 + j;
            g_gates[(size_t)row * NGATE + col] = acc[i][j] + bias[col];
        }
    }
}

// ---------------- LSTM pointwise --------------------------------------------
__global__ void lstm_kernel(const float* __restrict__ c_in,
                            float* __restrict__ h_out, float* __restrict__ c_out) {
    int t = blockIdx.x * blockDim.x + threadIdx.x;
    if (t >= BN * H_) return;
    int r = t >> 7, h = t & 127;
    const float* g = g_gates + (size_t)r * NGATE;
    float i  = sigmoidf_(g[h]);
    float f  = sigmoidf_(g[128 + h]);
    float o  = sigmoidf_(g[256 + h]);
    float gg = tanhf(g[384 + h]);
    float cn = f * c_in[t] + i * gg;
    c_out[t] = cn;
    h_out[t] = o * tanhf(cn);
}

// ---------------- attention energy + enc·pw2, one pass over enc -------------
// energy[s,b,n] = sum_j tanh(enc[s,b,n]·W[:,j] + b[j]) * out[b,n,j]
// dpw[s,b,n]    = enc[s,b,n]·proj_w[128:256]
// W is streamed through L1 via __ldg (64 KB, L1-resident within the launch);
// static smem only ~4.5 KB -> no cudaFuncSetAttribute needed anywhere.
#define EROWS 8
__global__ __launch_bounds__(128) void energy_kernel(
    const float* __restrict__ enc, const float* __restrict__ attn_w,
    const float* __restrict__ attn_b, const float* __restrict__ proj_w,
    const float* __restrict__ hout) {
    __shared__ float sE[128 * EROWS];     // [k=128][l=8]
    __shared__ float red[2 * 4 * EROWS];  // [2][warp=4][l=8]

    int tid = threadIdx.x;
    int lane = tid & 31, warp = tid >> 5;
    float bj   = attn_b[tid];
    float pw2  = proj_w[128 + tid];

    int totalGroups = (S_ * BN) / EROWS;
    for (int gidx = blockIdx.x; gidx < totalGroups; gidx += gridDim.x) {
        size_t row0 = (size_t)gidx * EROWS;
        // transpose-load 8 enc rows: sE[k][l]
#pragma unroll
        for (int l = 0; l < EROWS; l++)
            sE[tid * EROWS + l] = enc[(row0 + l) * H_ + tid];
        __syncthreads();

        float acc[EROWS];
#pragma unroll
        for (int l = 0; l < EROWS; l++) acc[l] = 0.f;
#pragma unroll 4
        for (int k = 0; k < 128; k++) {
            float w = __ldg(&attn_w[k * 128 + tid]);
            float4 e0 = *reinterpret_cast<const float4*>(&sE[k * EROWS]);
            float4 e1 = *reinterpret_cast<const float4*>(&sE[k * EROWS + 4]);
            acc[0] += e0.x * w; acc[1] += e0.y * w;
            acc[2] += e0.z * w; acc[3] += e0.w * w;
            acc[4] += e1.x * w; acc[5] += e1.y * w;
            acc[6] += e1.z * w; acc[7] += e1.w * w;
        }

        float e_part[EROWS], d_part[EROWS];
#pragma unroll
        for (int l = 0; l < EROWS; l++) {
            size_t gr = row0 + l;
            int bn = (int)(gr & (BN - 1));    // gr % (B*N), BN = 65536 pow2
            float oj = hout[(size_t)bn * H_ + tid];
            float tv = tanhf(acc[l] + bj);
            e_part[l] = tv * oj;
            d_part[l] = sE[tid * EROWS + l] * pw2;
        }
#pragma unroll
        for (int l = 0; l < EROWS; l++) {
#pragma unroll
            for (int off = 16; off > 0; off >>= 1) {
                e_part[l] += __shfl_xor_sync(0xffffffffu, e_part[l], off);
                d_part[l] += __shfl_xor_sync(0xffffffffu, d_part[l], off);
            }
        }
        if (lane == 0) {
#pragma unroll
            for (int l = 0; l < EROWS; l++) {
                red[(0 * 4 + warp) * EROWS + l] = e_part[l];
                red[(1 * 4 + warp) * EROWS + l] = d_part[l];
            }
        }
        __syncthreads();
        if (tid < EROWS) {
            float e = 0.f, d = 0.f;
#pragma unroll
            for (int w = 0; w < 4; w++) {
                e += red[(0 * 4 + w) * EROWS + tid];
                d += red[(1 * 4 + w) * EROWS + tid];
            }
            size_t gr = row0 + tid;
            g_energy[gr] = e;
            g_dpw[gr] = d;
        }
        __syncthreads();
    }
}

// ---------------- softmax over S + attw + final projection ------------------
__global__ void softmax_out_kernel(const float* __restrict__ proj_w,
                                   const float* __restrict__ proj_b,
                                   const float* __restrict__ hout,
                                   float* __restrict__ out0,
                                   float* __restrict__ attw) {
    int gwarp = (blockIdx.x * blockDim.x + threadIdx.x) >> 5;
    int lane = threadIdx.x & 31;
    if (gwarp >= BN) return;
    int bn = gwarp;

    float e = (lane < S_) ? g_energy[lane * BN + bn] : -1e30f;
    float m = e;
#pragma unroll
    for (int off = 16; off > 0; off >>= 1)
        m = fmaxf(m, __shfl_xor_sync(0xffffffffu, m, off));
    float p = (lane < S_) ? expf(e - m) : 0.f;
    float s = p;
#pragma unroll
    for (int off = 16; off > 0; off >>= 1)
        s += __shfl_xor_sync(0xffffffffu, s, off);
    float a = p / s;
    if (lane < S_) attw[(size_t)bn * S_ + lane] = a;

    float acc = (lane < S_) ? a * g_dpw[lane * BN + bn] : 0.f;
#pragma unroll
    for (int j = 0; j < 4; j++) {
        int col = lane + j * 32;
        acc += hout[(size_t)bn * H_ + col] * proj_w[col];
    }
#pragma unroll
    for (int off = 16; off > 0; off >>= 1)
        acc += __shfl_xor_sync(0xffffffffu, acc, off);
    if (lane == 0) out0[bn] = acc + proj_b[0];
}

// ---------------- orchestration: kernel launches ONLY ----------------------
extern "C" void kernel_launch(void* const* d_in, const int* in_sizes, int n_in,
                              void* d_out, int out_size) {
    const float* inputs  = (const float*)d_in[0];
    const float* enc     = (const float*)d_in[1];
    const float* hidden  = (const float*)d_in[2];
    const float* cell    = (const float*)d_in[3];
    const float* sup     = (const float*)d_in[4];
    const float* w0      = (const float*)d_in[5];
    const float* b0      = (const float*)d_in[6];
    const float* w1      = (const float*)d_in[7];
    const float* b1      = (const float*)d_in[8];
    const float* attn_w  = (const float*)d_in[9];
    const float* attn_b  = (const float*)d_in[10];
    const float* proj_w  = (const float*)d_in[11];
    const float* proj_b  = (const float*)d_in[12];
    float* out = (float*)d_out;

    float* hs0 = out + HS_OFF;
    float* hs1 = out + HS_OFF + (size_t)BN * H_;
    float* cs0 = out + CS_OFF;
    float* cs1 = out + CS_OFF + (size_t)BN * H_;
    float* attw = out + ATT_OFF;

    // 1. sparse structure of support
    build_csr_kernel<<<(N_ + 255) / 256, 256>>>(sup);

    // ---- layer 0 ----
    fill_x0_l0_kernel<<<(BN * 129 + 255) / 256, 256>>>(inputs, hidden);
    zero_pad_l0_kernel<<<(BN * 5 + 255) / 256, 256>>>();
    spmm_kernel<<<dim3(N_, B_), 128>>>(K0_PAD, 0, 129, -1, 129, 0);
    spmm_kernel<<<dim3(N_, B_), 128>>>(K0_PAD, 129, 258, 0, 129, 1);
    sgemm_kernel<<<dim3(NGATE / 128, BN / 128), 256>>>(w0, b0, K0_PAD, K0_REAL, K0_PAD);
    lstm_kernel<<<(BN * H_ + 255) / 256, 256>>>(cell, hs0, cs0);

    // ---- layer 1 ----
    fill_x0_l1_kernel<<<(BN * 256 + 255) / 256, 256>>>(hs0, hidden + (size_t)BN * H_);
    spmm_kernel<<<dim3(N_, B_), 128>>>(K1_, 0, 256, -1, 256, 0);
    spmm_kernel<<<dim3(N_, B_), 128>>>(K1_, 256, 512, 0, 256, 1);
    sgemm_kernel<<<dim3(NGATE / 128, BN / 128), 256>>>(w1, b1, K1_, K1_, K1_);
    lstm_kernel<<<(BN * H_ + 255) / 256, 256>>>(cell + (size_t)BN * H_, hs1, cs1);

    // ---- attention + projection ----
    energy_kernel<<<444, 128>>>(enc, attn_w, attn_b, proj_w, hs1);
    softmax_out_kernel<<<BN / 8, 256>>>(proj_w, proj_b, hs1, out, attw);
}

// round 5
// speedup vs baseline: 1.3274x; 1.3274x over previous
#include <cuda_runtime.h>
#include <cuda_bf16.h>
#include <cstdint>

#define B_   64
#define N_   1024
#define BN   65536
#define H_   128
#define S_   12
#define CSR_CAP 512

#define NGATE   512
#define K0_LDA  448      // layer0 feats lda: x0@0(129) x1@132(129) x2@264(129), pads zero
#define K1_LDA  768      // layer1 feats lda: x0@0(256) x1@256 x2@512

// d_out layout: [output 65536][hs 2*BN*H][cs 2*BN*H][attw BN*S]
#define HS_OFF   65536
#define CS_OFF   (65536 + 2 * BN * H_)
#define ATT_OFF  (CS_OFF + 2 * BN * H_)

// ---------------- scratch (device globals; no allocation allowed) ----------
__device__ float g_feats[(size_t)BN * 768];
__device__ float g_gates[(size_t)BN * 512];
__device__ float g_energy[S_ * BN];
__device__ float g_dpw[S_ * BN];
__device__ int   g_csr_cnt[N_];
__device__ int   g_csr_col[(size_t)N_ * CSR_CAP];
__device__ float g_csr_val[(size_t)N_ * CSR_CAP];
__device__ __nv_bfloat16 g_wt0h[(size_t)512 * K0_LDA];
__device__ __nv_bfloat16 g_wt0l[(size_t)512 * K0_LDA];
__device__ __nv_bfloat16 g_wt1h[(size_t)512 * K1_LDA];
__device__ __nv_bfloat16 g_wt1l[(size_t)512 * K1_LDA];

__device__ __forceinline__ float sigmoidf_(float x) { return 1.f / (1.f + expf(-x)); }

__device__ __forceinline__ uint32_t smem_u32(const void* p) {
    uint32_t a;
    asm("{ .reg .u64 t; cvta.to.shared.u64 t, %1; cvt.u32.u64 %0, t; }"
        : "=r"(a) : "l"(p));
    return a;
}
__device__ __forceinline__ void ldsm_x4(uint32_t* r, uint32_t addr) {
    asm volatile("ldmatrix.sync.aligned.m8n8.x4.shared.b16 {%0,%1,%2,%3}, [%4];"
                 : "=r"(r[0]), "=r"(r[1]), "=r"(r[2]), "=r"(r[3]) : "r"(addr));
}
__device__ __forceinline__ void mma_bf16(float* d, const uint32_t* a,
                                         const uint32_t* b) {
    asm volatile(
        "mma.sync.aligned.m16n8k16.row.col.f32.bf16.bf16.f32 "
        "{%0,%1,%2,%3}, {%4,%5,%6,%7}, {%8,%9}, {%0,%1,%2,%3};"
        : "+f"(d[0]), "+f"(d[1]), "+f"(d[2]), "+f"(d[3])
        : "r"(a[0]), "r"(a[1]), "r"(a[2]), "r"(a[3]), "r"(b[0]), "r"(b[1]));
}

// ---------------- CSR build ------------------------------------------------
__global__ void build_csr_kernel(const float* __restrict__ sup) {
    int n = blockIdx.x * blockDim.x + threadIdx.x;
    if (n >= N_) return;
    int cnt = 0;
    const float* row = sup + (size_t)n * N_;
    for (int m = 0; m < N_; m++) {
        float v = row[m];
        if (v != 0.f) {
            if (cnt < CSR_CAP) {
                g_csr_col[n * CSR_CAP + cnt] = m;
                g_csr_val[n * CSR_CAP + cnt] = v;
            }
            cnt++;
        }
    }
    g_csr_cnt[n] = cnt < CSR_CAP ? cnt : CSR_CAP;
}

// ---------------- W split/permute to bf16 hi/lo, transposed [n][k] ---------
__global__ void wsplit_kernel(const float* __restrict__ w, int Kpad, int layer) {
    int t = blockIdx.x * blockDim.x + threadIdx.x;
    if (t >= 512 * Kpad) return;
    int n = t / Kpad, k = t - n * Kpad;
    int r;
    if (layer == 0)
        r = (k < 129) ? k : (k >= 132 && k < 261) ? k - 3 : (k >= 264 && k < 393) ? k - 6 : -1;
    else
        r = (k < 768) ? k : -1;
    float v = (r >= 0) ? w[(size_t)r * NGATE + n] : 0.f;
    __nv_bfloat16 h = __float2bfloat16(v);
    __nv_bfloat16 l = __float2bfloat16(v - __bfloat162float(h));
    if (layer == 0) { g_wt0h[t] = h; g_wt0l[t] = l; }
    else            { g_wt1h[t] = h; g_wt1l[t] = l; }
}

// ---------------- fill x0 for layer 0 --------------------------------------
__global__ void fill_x0_l0_kernel(const float* __restrict__ inputs,
                                  const float* __restrict__ h0) {
    int t = blockIdx.x * blockDim.x + threadIdx.x;
    if (t >= BN * 129) return;
    int r = t / 129;
    int c = t - r * 129;
    float v = (c == 0) ? inputs[r] : h0[r * H_ + (c - 1)];
    g_feats[(size_t)r * K0_LDA + c] = v;
}
// zero pad cols: 129-131, 261-263, 393-447 (61 cols)
__global__ void zero_pad_l0_kernel() {
    int t = blockIdx.x * blockDim.x + threadIdx.x;
    if (t >= BN * 64) return;
    int r = t >> 6, j = t & 63;
    if (j >= 61) return;
    int col = (j < 3) ? 129 + j : (j < 6) ? 258 + j : 387 + j;
    g_feats[(size_t)r * K0_LDA + col] = 0.f;
}

// ---------------- fill x0 for layer 1 --------------------------------------
__global__ void fill_x0_l1_kernel(const float* __restrict__ h0new,
                                  const float* __restrict__ h1) {
    int t = blockIdx.x * blockDim.x + threadIdx.x;
    if (t >= BN * 256) return;
    int r = t >> 8;
    int c = t & 255;
    float v = (c < H_) ? h0new[r * H_ + c] : h1[r * H_ + (c - H_)];
    g_feats[(size_t)r * K1_LDA + c] = v;
}

// ---------------- vectorized sparse diffusion ------------------------------
__global__ __launch_bounds__(128) void spmmv_kernel(int ld, int srcCol, int dstCol,
                                                    int prevCol, int D4, int cheb) {
    __shared__ int   scol[CSR_CAP];
    __shared__ float sval[CSR_CAP];
    int n = blockIdx.x;
    int tid = threadIdx.x, bq = tid >> 5, tq = tid & 31;
    int cnt = g_csr_cnt[n];
    for (int i = tid; i < cnt; i += 128) {
        scol[i] = g_csr_col[n * CSR_CAP + i];
        sval[i] = g_csr_val[n * CSR_CAP + i];
    }
    __syncthreads();
    int b = blockIdx.y * 4 + bq;
    const float* srcB = g_feats + (size_t)b * N_ * ld + srcCol;
    size_t rbase = ((size_t)b * N_ + n) * ld;
    for (int d0 = tq * 4; d0 < D4; d0 += 128) {
        float4 acc = make_float4(0.f, 0.f, 0.f, 0.f);
        for (int i = 0; i < cnt; i++) {
            const float4 v = *(const float4*)(srcB + (size_t)scol[i] * ld + d0);
            float s = sval[i];
            acc.x += s * v.x; acc.y += s * v.y; acc.z += s * v.z; acc.w += s * v.w;
        }
        if (cheb) {
            float4 p = *(const float4*)(g_feats + rbase + prevCol + d0);
            acc.x = 2.f * acc.x - p.x; acc.y = 2.f * acc.y - p.y;
            acc.z = 2.f * acc.z - p.z; acc.w = 2.f * acc.w - p.w;
        }
        *(float4*)(g_feats + rbase + dstCol + d0) = acc;
    }
}

// ---------------- mma.sync split-bf16 gate GEMM ----------------------------
// gates[M,512] = feats[M,K] @ W[K,512] + bias, via bf16 hi/lo split (3 prod).
// Block 128x128, 256 thr = 8 warps (4x2), warp tile 32x64, k-chunk 16.
#define SROW 12   // smem row stride in uint32 (24 bf16 = 48 B)
__global__ __launch_bounds__(256) void gates_mma_kernel(const float* __restrict__ bias,
                                                        int lda, int nch, int layer) {
    __shared__ __align__(16) uint32_t sAh[128 * SROW];
    __shared__ __align__(16) uint32_t sAl[128 * SROW];
    __shared__ __align__(16) uint32_t sBh[128 * SROW];
    __shared__ __align__(16) uint32_t sBl[128 * SROW];

    const __nv_bfloat16* wt_hi = layer ? g_wt1h : g_wt0h;
    const __nv_bfloat16* wt_lo = layer ? g_wt1l : g_wt0l;

    int tid = threadIdx.x, lane = tid & 31, wid = tid >> 5;
    int warpM = wid & 3, warpN = wid >> 2;
    size_t rowBase = (size_t)blockIdx.x * 128;
    int colBase = blockIdx.y * 128;

    // ldmatrix addresses (fixed across chunks)
    uint32_t aAH[2], aAL[2], bAH[4], bAL[4];
#pragma unroll
    for (int am = 0; am < 2; am++) {
        int r = warpM * 32 + am * 16 + (lane & 15);
        int c = (lane >> 4) * 4;                  // uint32 offset (8 bf16)
        aAH[am] = smem_u32(&sAh[r * SROW + c]);
        aAL[am] = smem_u32(&sAl[r * SROW + c]);
    }
#pragma unroll
    for (int p = 0; p < 4; p++) {
        int quad = lane >> 3;
        int rowo = ((quad == 0 || quad == 1) ? 0 : 8) + (lane & 7);
        int c = (quad & 1) * 4;
        int n = warpN * 64 + p * 16 + rowo;
        bAH[p] = smem_u32(&sBh[n * SROW + c]);
        bAL[p] = smem_u32(&sBl[n * SROW + c]);
    }

    float acc[2][8][4];
#pragma unroll
    for (int i = 0; i < 2; i++)
#pragma unroll
        for (int j = 0; j < 8; j++)
#pragma unroll
            for (int q = 0; q < 4; q++) acc[i][j][q] = 0.f;

    int lr = tid >> 1;                 // 0..127
    int lh = (tid & 1) * 8;            // 0 or 8 (bf16 cols)
    const float* aSrc = g_feats + (rowBase + lr) * (size_t)lda + lh;
    const uint4* bSrcH = (const uint4*)(wt_hi + (size_t)(colBase + lr) * lda + lh);
    const uint4* bSrcL = (const uint4*)(wt_lo + (size_t)(colBase + lr) * lda + lh);
    uint32_t* aDstH = &sAh[lr * SROW + (lh >> 1)];
    uint32_t* aDstL = &sAl[lr * SROW + (lh >> 1)];
    uint32_t* bDstH = &sBh[lr * SROW + (lh >> 1)];
    uint32_t* bDstL = &sBl[lr * SROW + (lh >> 1)];

    for (int kc = 0; kc < nch; kc++) {
        // ---- stage A (fp32 -> bf16 hi/lo) ----
        {
            const float4* s = (const float4*)(aSrc + kc * 16);
            float4 v0 = s[0], v1 = s[1];
            float vv[8] = {v0.x, v0.y, v0.z, v0.w, v1.x, v1.y, v1.z, v1.w};
            uint32_t hh[4], ll[4];
#pragma unroll
            for (int i = 0; i < 4; i++) {
                float x = vv[2 * i], y = vv[2 * i + 1];
                __nv_bfloat162 hp = __floats2bfloat162_rn(x, y);
                float lx = x - __bfloat162float(hp.x);
                float ly = y - __bfloat162float(hp.y);
                __nv_bfloat162 lp = __floats2bfloat162_rn(lx, ly);
                hh[i] = *(uint32_t*)&hp;
                ll[i] = *(uint32_t*)&lp;
            }
            *(uint4*)aDstH = make_uint4(hh[0], hh[1], hh[2], hh[3]);
            *(uint4*)aDstL = make_uint4(ll[0], ll[1], ll[2], ll[3]);
            // ---- stage B (precomputed bf16 hi/lo) ----
            *(uint4*)bDstH = bSrcH[kc * 2];
            *(uint4*)bDstL = bSrcL[kc * 2];
        }
        __syncthreads();

        uint32_t aH[2][4], aL[2][4], bH[4][4], bL[4][4];
#pragma unroll
        for (int am = 0; am < 2; am++) { ldsm_x4(aH[am], aAH[am]); ldsm_x4(aL[am], aAL[am]); }
#pragma unroll
        for (int p = 0; p < 4; p++)   { ldsm_x4(bH[p], bAH[p]);   ldsm_x4(bL[p], bAL[p]); }

#pragma unroll
        for (int am = 0; am < 2; am++) {
#pragma unroll
            for (int p = 0; p < 4; p++) {
                // tile 2p   : b regs [0],[1] ; tile 2p+1 : [2],[3]
                mma_bf16(acc[am][2 * p],     aH[am], &bH[p][0]);
                mma_bf16(acc[am][2 * p],     aL[am], &bH[p][0]);
                mma_bf16(acc[am][2 * p],     aH[am], &bL[p][0]);
                mma_bf16(acc[am][2 * p + 1], aH[am], &bH[p][2]);
                mma_bf16(acc[am][2 * p + 1], aL[am], &bH[p][2]);
                mma_bf16(acc[am][2 * p + 1], aH[am], &bL[p][2]);
            }
        }
        __syncthreads();
    }

    // ---- epilogue ----
#pragma unroll
    for (int am = 0; am < 2; am++) {
        size_t row0 = rowBase + warpM * 32 + am * 16 + (lane >> 2);
#pragma unroll
        for (int bn = 0; bn < 8; bn++) {
            int col = colBase + warpN * 64 + bn * 8 + (lane & 3) * 2;
            float2 bv = *(const float2*)(bias + col);
            float2 v0 = make_float2(acc[am][bn][0] + bv.x, acc[am][bn][1] + bv.y);
            float2 v1 = make_float2(acc[am][bn][2] + bv.x, acc[am][bn][3] + bv.y);
            *(float2*)(g_gates + row0 * NGATE + col) = v0;
            *(float2*)(g_gates + (row0 + 8) * NGATE + col) = v1;
        }
    }
}

// ---------------- LSTM pointwise -------------------------------------------
__global__ void lstm_kernel(const float* __restrict__ c_in,
                            float* __restrict__ h_out, float* __restrict__ c_out) {
    int t = blockIdx.x * blockDim.x + threadIdx.x;
    if (t >= BN * H_) return;
    int r = t >> 7, h = t & 127;
    const float* g = g_gates + (size_t)r * NGATE;
    float i  = sigmoidf_(g[h]);
    float f  = sigmoidf_(g[128 + h]);
    float o  = sigmoidf_(g[256 + h]);
    float gg = tanhf(g[384 + h]);
    float cn = f * c_in[t] + i * gg;
    c_out[t] = cn;
    h_out[t] = o * tanhf(cn);
}

// ---------------- attention energy + enc.pw2, one pass over enc ------------
#define EROWS 8
__global__ __launch_bounds__(128) void energy_kernel(
    const float* __restrict__ enc, const float* __restrict__ attn_w,
    const float* __restrict__ attn_b, const float* __restrict__ proj_w,
    const float* __restrict__ hout) {
    __shared__ float sE[128 * EROWS];
    __shared__ float red[2 * 4 * EROWS];

    int tid = threadIdx.x;
    int lane = tid & 31, warp = tid >> 5;
    float bj  = attn_b[tid];
    float pw2 = proj_w[128 + tid];

    int totalGroups = (S_ * BN) / EROWS;
    for (int gidx = blockIdx.x; gidx < totalGroups; gidx += gridDim.x) {
        size_t row0 = (size_t)gidx * EROWS;
#pragma unroll
        for (int l = 0; l < EROWS; l++)
            sE[tid * EROWS + l] = enc[(row0 + l) * H_ + tid];
        __syncthreads();

        float acc[EROWS];
#pragma unroll
        for (int l = 0; l < EROWS; l++) acc[l] = 0.f;
#pragma unroll 4
        for (int k = 0; k < 128; k++) {
            float w = __ldg(&attn_w[k * 128 + tid]);
            float4 e0 = *reinterpret_cast<const float4*>(&sE[k * EROWS]);
            float4 e1 = *reinterpret_cast<const float4*>(&sE[k * EROWS + 4]);
            acc[0] += e0.x * w; acc[1] += e0.y * w;
            acc[2] += e0.z * w; acc[3] += e0.w * w;
            acc[4] += e1.x * w; acc[5] += e1.y * w;
            acc[6] += e1.z * w; acc[7] += e1.w * w;
        }

        float e_part[EROWS], d_part[EROWS];
#pragma unroll
        for (int l = 0; l < EROWS; l++) {
            size_t gr = row0 + l;
            int bn = (int)(gr & (BN - 1));
            float oj = hout[(size_t)bn * H_ + tid];
            float tv = tanhf(acc[l] + bj);
            e_part[l] = tv * oj;
            d_part[l] = sE[tid * EROWS + l] * pw2;
        }
#pragma unroll
        for (int l = 0; l < EROWS; l++) {
#pragma unroll
            for (int off = 16; off > 0; off >>= 1) {
                e_part[l] += __shfl_xor_sync(0xffffffffu, e_part[l], off);
                d_part[l] += __shfl_xor_sync(0xffffffffu, d_part[l], off);
            }
        }
        if (lane == 0) {
#pragma unroll
            for (int l = 0; l < EROWS; l++) {
                red[(0 * 4 + warp) * EROWS + l] = e_part[l];
                red[(1 * 4 + warp) * EROWS + l] = d_part[l];
            }
        }
        __syncthreads();
        if (tid < EROWS) {
            float e = 0.f, d = 0.f;
#pragma unroll
            for (int w = 0; w < 4; w++) {
                e += red[(0 * 4 + w) * EROWS + tid];
                d += red[(1 * 4 + w) * EROWS + tid];
            }
            size_t gr = row0 + tid;
            g_energy[gr] = e;
            g_dpw[gr] = d;
        }
        __syncthreads();
    }
}

// ---------------- softmax over S + attw + final projection -----------------
__global__ void softmax_out_kernel(const float* __restrict__ proj_w,
                                   const float* __restrict__ proj_b,
                                   const float* __restrict__ hout,
                                   float* __restrict__ out0,
                                   float* __restrict__ attw) {
    int gwarp = (blockIdx.x * blockDim.x + threadIdx.x) >> 5;
    int lane = threadIdx.x & 31;
    if (gwarp >= BN) return;
    int bn = gwarp;

    float e = (lane < S_) ? g_energy[lane * BN + bn] : -1e30f;
    float m = e;
#pragma unroll
    for (int off = 16; off > 0; off >>= 1)
        m = fmaxf(m, __shfl_xor_sync(0xffffffffu, m, off));
    float p = (lane < S_) ? expf(e - m) : 0.f;
    float s = p;
#pragma unroll
    for (int off = 16; off > 0; off >>= 1)
        s += __shfl_xor_sync(0xffffffffu, s, off);
    float a = p / s;
    if (lane < S_) attw[(size_t)bn * S_ + lane] = a;

    float acc = (lane < S_) ? a * g_dpw[lane * BN + bn] : 0.f;
#pragma unroll
    for (int j = 0; j < 4; j++) {
        int col = lane + j * 32;
        acc += hout[(size_t)bn * H_ + col] * proj_w[col];
    }
#pragma unroll
    for (int off = 16; off > 0; off >>= 1)
        acc += __shfl_xor_sync(0xffffffffu, acc, off);
    if (lane == 0) out0[bn] = acc + proj_b[0];
}

// ---------------- orchestration: kernel launches ONLY ----------------------
extern "C" void kernel_launch(void* const* d_in, const int* in_sizes, int n_in,
                              void* d_out, int out_size) {
    const float* inputs  = (const float*)d_in[0];
    const float* enc     = (const float*)d_in[1];
    const float* hidden  = (const float*)d_in[2];
    const float* cell    = (const float*)d_in[3];
    const float* sup     = (const float*)d_in[4];
    const float* w0      = (const float*)d_in[5];
    const float* b0      = (const float*)d_in[6];
    const float* w1      = (const float*)d_in[7];
    const float* b1      = (const float*)d_in[8];
    const float* attn_w  = (const float*)d_in[9];
    const float* attn_b  = (const float*)d_in[10];
    const float* proj_w  = (const float*)d_in[11];
    const float* proj_b  = (const float*)d_in[12];
    float* out = (float*)d_out;

    float* hs0 = out + HS_OFF;
    float* hs1 = out + HS_OFF + (size_t)BN * H_;
    float* cs0 = out + CS_OFF;
    float* cs1 = out + CS_OFF + (size_t)BN * H_;
    float* attw = out + ATT_OFF;

    // sparse structure + weight splits
    build_csr_kernel<<<(N_ + 255) / 256, 256>>>(sup);
    wsplit_kernel<<<(512 * K0_LDA + 255) / 256, 256>>>(w0, K0_LDA, 0);
    wsplit_kernel<<<(512 * K1_LDA + 255) / 256, 256>>>(w1, K1_LDA, 1);

    // ---- layer 0 ----
    fill_x0_l0_kernel<<<(BN * 129 + 255) / 256, 256>>>(inputs, hidden);
    zero_pad_l0_kernel<<<(BN * 64 + 255) / 256, 256>>>();
    spmmv_kernel<<<dim3(N_, B_ / 4), 128>>>(K0_LDA, 0, 132, -1, 132, 0);
    spmmv_kernel<<<dim3(N_, B_ / 4), 128>>>(K0_LDA, 132, 264, 0, 132, 1);
    gates_mma_kernel<<<dim3(BN / 128, 4), 256>>>(b0, K0_LDA, K0_LDA / 16, 0);
    lstm_kernel<<<(BN * H_ + 255) / 256, 256>>>(cell, hs0, cs0);

    // ---- layer 1 ----
    fill_x0_l1_kernel<<<(BN * 256 + 255) / 256, 256>>>(hs0, hidden + (size_t)BN * H_);
    spmmv_kernel<<<dim3(N_, B_ / 4), 128>>>(K1_LDA, 0, 256, -1, 256, 0);
    spmmv_kernel<<<dim3(N_, B_ / 4), 128>>>(K1_LDA, 256, 512, 0, 256, 1);
    gates_mma_kernel<<<dim3(BN / 128, 4), 256>>>(b1, K1_LDA, K1_LDA / 16, 1);
    lstm_kernel<<<(BN * H_ + 255) / 256, 256>>>(cell + (size_t)BN * H_, hs1, cs1);

    // ---- attention + projection ----
    energy_kernel<<<444, 128>>>(enc, attn_w, attn_b, proj_w, hs1);
    softmax_out_kernel<<<BN / 8, 256>>>(proj_w, proj_b, hs1, out, attw);
}

// round 6
// speedup vs baseline: 2.1830x; 1.6446x over previous
#include <cuda_runtime.h>
#include <cuda_bf16.h>
#include <cstdint>

#define B_   64
#define N_   1024
#define BN   65536
#define H_   128
#define S_   12
#define CSR_CAP 512

#define NGATE   512
#define K0_LDA  448      // layer0 feats lda: x0@0(129) x1@132(129) x2@264(129), pads zero
#define K1_LDA  768      // layer1 feats lda: x0@0(256) x1@256 x2@512

// d_out layout: [output 65536][hs 2*BN*H][cs 2*BN*H][attw BN*S]
#define HS_OFF   65536
#define CS_OFF   (65536 + 2 * BN * H_)
#define ATT_OFF  (CS_OFF + 2 * BN * H_)

// ---------------- scratch (device globals; no allocation allowed) ----------
__device__ float g_feats[(size_t)BN * 768];
__device__ float g_gates[(size_t)BN * 512];
__device__ float g_energy[S_ * BN];
__device__ float g_dpw[S_ * BN];
__device__ int   g_csr_cnt[N_];
__device__ int   g_csr_col[(size_t)N_ * CSR_CAP];
__device__ float g_csr_val[(size_t)N_ * CSR_CAP];
__device__ __nv_bfloat16 g_wt0h[(size_t)512 * K0_LDA];
__device__ __nv_bfloat16 g_wt0l[(size_t)512 * K0_LDA];
__device__ __nv_bfloat16 g_wt1h[(size_t)512 * K1_LDA];
__device__ __nv_bfloat16 g_wt1l[(size_t)512 * K1_LDA];
__device__ __nv_bfloat16 g_awh[(size_t)128 * 128];   // attn_w^T hi
__device__ __nv_bfloat16 g_awl[(size_t)128 * 128];   // attn_w^T lo

__device__ __forceinline__ float sigmoidf_(float x) { return 1.f / (1.f + expf(-x)); }

__device__ __forceinline__ uint32_t smem_u32(const void* p) {
    uint32_t a;
    asm("{ .reg .u64 t; cvta.to.shared.u64 t, %1; cvt.u32.u64 %0, t; }"
        : "=r"(a) : "l"(p));
    return a;
}
__device__ __forceinline__ void ldsm_x4(uint32_t* r, uint32_t addr) {
    asm volatile("ldmatrix.sync.aligned.m8n8.x4.shared.b16 {%0,%1,%2,%3}, [%4];"
                 : "=r"(r[0]), "=r"(r[1]), "=r"(r[2]), "=r"(r[3]) : "r"(addr));
}
__device__ __forceinline__ void mma_bf16(float* d, const uint32_t* a,
                                         const uint32_t* b) {
    asm volatile(
        "mma.sync.aligned.m16n8k16.row.col.f32.bf16.bf16.f32 "
        "{%0,%1,%2,%3}, {%4,%5,%6,%7}, {%8,%9}, {%0,%1,%2,%3};"
        : "+f"(d[0]), "+f"(d[1]), "+f"(d[2]), "+f"(d[3])
        : "r"(a[0]), "r"(a[1]), "r"(a[2]), "r"(a[3]), "r"(b[0]), "r"(b[1]));
}

// ---------------- CSR build ------------------------------------------------
__global__ void build_csr_kernel(const float* __restrict__ sup) {
    int n = blockIdx.x * blockDim.x + threadIdx.x;
    if (n >= N_) return;
    int cnt = 0;
    const float* row = sup + (size_t)n * N_;
    for (int m = 0; m < N_; m++) {
        float v = row[m];
        if (v != 0.f) {
            if (cnt < CSR_CAP) {
                g_csr_col[n * CSR_CAP + cnt] = m;
                g_csr_val[n * CSR_CAP + cnt] = v;
            }
            cnt++;
        }
    }
    g_csr_cnt[n] = cnt < CSR_CAP ? cnt : CSR_CAP;
}

// ---------------- W split/permute to bf16 hi/lo, transposed [n][k] ---------
__global__ void wsplit_kernel(const float* __restrict__ w, int Kpad, int layer) {
    int t = blockIdx.x * blockDim.x + threadIdx.x;
    if (t >= 512 * Kpad) return;
    int n = t / Kpad, k = t - n * Kpad;
    int r;
    if (layer == 0)
        r = (k < 129) ? k : (k >= 132 && k < 261) ? k - 3 : (k >= 264 && k < 393) ? k - 6 : -1;
    else
        r = (k < 768) ? k : -1;
    float v = (r >= 0) ? w[(size_t)r * NGATE + n] : 0.f;
    __nv_bfloat16 h = __float2bfloat16(v);
    __nv_bfloat16 l = __float2bfloat16(v - __bfloat162float(h));
    if (layer == 0) { g_wt0h[t] = h; g_wt0l[t] = l; }
    else            { g_wt1h[t] = h; g_wt1l[t] = l; }
}

// attn_w [k=128][n=128] -> transposed hi/lo [n][k]
__global__ void awsplit_kernel(const float* __restrict__ aw) {
    int t = blockIdx.x * blockDim.x + threadIdx.x;
    if (t >= 128 * 128) return;
    int n = t >> 7, k = t & 127;
    float v = aw[k * 128 + n];
    __nv_bfloat16 h = __float2bfloat16(v);
    __nv_bfloat16 l = __float2bfloat16(v - __bfloat162float(h));
    g_awh[t] = h;
    g_awl[t] = l;
}

// ---------------- fill x0 for layer 0 --------------------------------------
__global__ void fill_x0_l0_kernel(const float* __restrict__ inputs,
                                  const float* __restrict__ h0) {
    int t = blockIdx.x * blockDim.x + threadIdx.x;
    if (t >= BN * 129) return;
    int r = t / 129;
    int c = t - r * 129;
    float v = (c == 0) ? inputs[r] : h0[r * H_ + (c - 1)];
    g_feats[(size_t)r * K0_LDA + c] = v;
}
// zero pad cols: 129-131, 261-263, 393-447 (61 cols)
__global__ void zero_pad_l0_kernel() {
    int t = blockIdx.x * blockDim.x + threadIdx.x;
    if (t >= BN * 64) return;
    int r = t >> 6, j = t & 63;
    if (j >= 61) return;
    int col = (j < 3) ? 129 + j : (j < 6) ? 258 + j : 387 + j;
    g_feats[(size_t)r * K0_LDA + col] = 0.f;
}

// ---------------- fill x0 for layer 1 --------------------------------------
__global__ void fill_x0_l1_kernel(const float* __restrict__ h0new,
                                  const float* __restrict__ h1) {
    int t = blockIdx.x * blockDim.x + threadIdx.x;
    if (t >= BN * 256) return;
    int r = t >> 8;
    int c = t & 255;
    float v = (c < H_) ? h0new[r * H_ + c] : h1[r * H_ + (c - H_)];
    g_feats[(size_t)r * K1_LDA + c] = v;
}

// ---------------- vectorized sparse diffusion ------------------------------
__global__ __launch_bounds__(128) void spmmv_kernel(int ld, int srcCol, int dstCol,
                                                    int prevCol, int D4, int cheb) {
    __shared__ int   scol[CSR_CAP];
    __shared__ float sval[CSR_CAP];
    int n = blockIdx.x;
    int tid = threadIdx.x, bq = tid >> 5, tq = tid & 31;
    int cnt = g_csr_cnt[n];
    for (int i = tid; i < cnt; i += 128) {
        scol[i] = g_csr_col[n * CSR_CAP + i];
        sval[i] = g_csr_val[n * CSR_CAP + i];
    }
    __syncthreads();
    int b = blockIdx.y * 4 + bq;
    const float* srcB = g_feats + (size_t)b * N_ * ld + srcCol;
    size_t rbase = ((size_t)b * N_ + n) * ld;
    for (int d0 = tq * 4; d0 < D4; d0 += 128) {
        float4 acc = make_float4(0.f, 0.f, 0.f, 0.f);
        for (int i = 0; i < cnt; i++) {
            const float4 v = *(const float4*)(srcB + (size_t)scol[i] * ld + d0);
            float s = sval[i];
            acc.x += s * v.x; acc.y += s * v.y; acc.z += s * v.z; acc.w += s * v.w;
        }
        if (cheb) {
            float4 p = *(const float4*)(g_feats + rbase + prevCol + d0);
            acc.x = 2.f * acc.x - p.x; acc.y = 2.f * acc.y - p.y;
            acc.z = 2.f * acc.z - p.z; acc.w = 2.f * acc.w - p.w;
        }
        *(float4*)(g_feats + rbase + dstCol + d0) = acc;
    }
}

// ---------------- mma.sync split-bf16 gate GEMM (software-pipelined) -------
#define SROW 12   // smem row stride in uint32 (24 bf16 = 48 B)
__global__ __launch_bounds__(256) void gates_mma_kernel(const float* __restrict__ bias,
                                                        int lda, int nch, int layer) {
    __shared__ __align__(16) uint32_t sAh[128 * SROW];
    __shared__ __align__(16) uint32_t sAl[128 * SROW];
    __shared__ __align__(16) uint32_t sBh[128 * SROW];
    __shared__ __align__(16) uint32_t sBl[128 * SROW];

    const __nv_bfloat16* wt_hi = layer ? g_wt1h : g_wt0h;
    const __nv_bfloat16* wt_lo = layer ? g_wt1l : g_wt0l;

    int tid = threadIdx.x, lane = tid & 31, wid = tid >> 5;
    int warpM = wid & 3, warpN = wid >> 2;
    size_t rowBase = (size_t)blockIdx.x * 128;
    int colBase = blockIdx.y * 128;

    uint32_t aAH[2], aAL[2], bAH[4], bAL[4];
#pragma unroll
    for (int am = 0; am < 2; am++) {
        int r = warpM * 32 + am * 16 + (lane & 15);
        int c = (lane >> 4) * 4;
        aAH[am] = smem_u32(&sAh[r * SROW + c]);
        aAL[am] = smem_u32(&sAl[r * SROW + c]);
    }
#pragma unroll
    for (int p = 0; p < 4; p++) {
        int quad = lane >> 3;
        int rowo = ((quad == 0 || quad == 1) ? 0 : 8) + (lane & 7);
        int c = (quad & 1) * 4;
        int n = warpN * 64 + p * 16 + rowo;
        bAH[p] = smem_u32(&sBh[n * SROW + c]);
        bAL[p] = smem_u32(&sBl[n * SROW + c]);
    }

    float acc[2][8][4];
#pragma unroll
    for (int i = 0; i < 2; i++)
#pragma unroll
        for (int j = 0; j < 8; j++)
#pragma unroll
            for (int q = 0; q < 4; q++) acc[i][j][q] = 0.f;

    int lr = tid >> 1;
    int lh = (tid & 1) * 8;
    const float* aSrc = g_feats + (rowBase + lr) * (size_t)lda + lh;
    const uint4* bSrcH = (const uint4*)(wt_hi + (size_t)(colBase + lr) * lda + lh);
    const uint4* bSrcL = (const uint4*)(wt_lo + (size_t)(colBase + lr) * lda + lh);
    uint32_t* aDstH = &sAh[lr * SROW + (lh >> 1)];
    uint32_t* aDstL = &sAl[lr * SROW + (lh >> 1)];
    uint32_t* bDstH = &sBh[lr * SROW + (lh >> 1)];
    uint32_t* bDstL = &sBl[lr * SROW + (lh >> 1)];

    // prefetch chunk 0
    float4 pv0 = ((const float4*)aSrc)[0];
    float4 pv1 = ((const float4*)aSrc)[1];
    uint4 pbh = bSrcH[0], pbl = bSrcL[0];

    for (int kc = 0; kc < nch; kc++) {
        // stage current chunk
        {
            float vv[8] = {pv0.x, pv0.y, pv0.z, pv0.w, pv1.x, pv1.y, pv1.z, pv1.w};
            uint32_t hh[4], ll[4];
#pragma unroll
            for (int i = 0; i < 4; i++) {
                float x = vv[2 * i], y = vv[2 * i + 1];
                __nv_bfloat162 hp = __floats2bfloat162_rn(x, y);
                float lx = x - __bfloat162float(hp.x);
                float ly = y - __bfloat162float(hp.y);
                __nv_bfloat162 lp = __floats2bfloat162_rn(lx, ly);
                hh[i] = *(uint32_t*)&hp;
                ll[i] = *(uint32_t*)&lp;
            }
            *(uint4*)aDstH = make_uint4(hh[0], hh[1], hh[2], hh[3]);
            *(uint4*)aDstL = make_uint4(ll[0], ll[1], ll[2], ll[3]);
            *(uint4*)bDstH = pbh;
            *(uint4*)bDstL = pbl;
        }
        __syncthreads();
        // prefetch next chunk (overlaps mma below)
        if (kc + 1 < nch) {
            const float4* s = (const float4*)(aSrc + (kc + 1) * 16);
            pv0 = s[0]; pv1 = s[1];
            pbh = bSrcH[(kc + 1) * 2];
            pbl = bSrcL[(kc + 1) * 2];
        }

        uint32_t aH[2][4], aL[2][4], bH[4][4], bL[4][4];
#pragma unroll
        for (int am = 0; am < 2; am++) { ldsm_x4(aH[am], aAH[am]); ldsm_x4(aL[am], aAL[am]); }
#pragma unroll
        for (int p = 0; p < 4; p++)   { ldsm_x4(bH[p], bAH[p]);   ldsm_x4(bL[p], bAL[p]); }

#pragma unroll
        for (int am = 0; am < 2; am++) {
#pragma unroll
            for (int p = 0; p < 4; p++) {
                mma_bf16(acc[am][2 * p],     aH[am], &bH[p][0]);
                mma_bf16(acc[am][2 * p],     aL[am], &bH[p][0]);
                mma_bf16(acc[am][2 * p],     aH[am], &bL[p][0]);
                mma_bf16(acc[am][2 * p + 1], aH[am], &bH[p][2]);
                mma_bf16(acc[am][2 * p + 1], aL[am], &bH[p][2]);
                mma_bf16(acc[am][2 * p + 1], aH[am], &bL[p][2]);
            }
        }
        __syncthreads();
    }

#pragma unroll
    for (int am = 0; am < 2; am++) {
        size_t row0 = rowBase + warpM * 32 + am * 16 + (lane >> 2);
#pragma unroll
        for (int bn = 0; bn < 8; bn++) {
            int col = colBase + warpN * 64 + bn * 8 + (lane & 3) * 2;
            float2 bv = *(const float2*)(bias + col);
            float2 v0 = make_float2(acc[am][bn][0] + bv.x, acc[am][bn][1] + bv.y);
            float2 v1 = make_float2(acc[am][bn][2] + bv.x, acc[am][bn][3] + bv.y);
            *(float2*)(g_gates + row0 * NGATE + col) = v0;
            *(float2*)(g_gates + (row0 + 8) * NGATE + col) = v1;
        }
    }
}

// ---------------- LSTM pointwise -------------------------------------------
__global__ void lstm_kernel(const float* __restrict__ c_in,
                            float* __restrict__ h_out, float* __restrict__ c_out) {
    int t = blockIdx.x * blockDim.x + threadIdx.x;
    if (t >= BN * H_) return;
    int r = t >> 7, h = t & 127;
    const float* g = g_gates + (size_t)r * NGATE;
    float i  = sigmoidf_(g[h]);
    float f  = sigmoidf_(g[128 + h]);
    float o  = sigmoidf_(g[256 + h]);
    float gg = tanhf(g[384 + h]);
    float cn = f * c_in[t] + i * gg;
    c_out[t] = cn;
    h_out[t] = o * tanhf(cn);
}

// ---------------- mma-based attention energy + dpw, one pass over enc ------
// T = enc[row,128] @ attn_w[128,128]; energy[row] = sum_j tanh(T+b)_j * hout[bn,j]
// dpw[row] = enc[row,:] . proj_w[128:256]   (fp32, folded into the loader)
__global__ __launch_bounds__(256) void energy_mma_kernel(
    const float* __restrict__ enc, const float* __restrict__ attn_b,
    const float* __restrict__ proj_w, const float* __restrict__ hout) {
    __shared__ __align__(16) uint32_t sAh[128 * SROW];
    __shared__ __align__(16) uint32_t sAl[128 * SROW];
    __shared__ __align__(16) uint32_t sBh[128 * SROW];
    __shared__ __align__(16) uint32_t sBl[128 * SROW];
    __shared__ float sred[4][2][2][8];

    int tid = threadIdx.x, lane = tid & 31, wid = tid >> 5;
    int warpM = wid & 3, warpN = wid >> 2;
    size_t tileBase = (size_t)blockIdx.x * 128;

    uint32_t aAH[2], aAL[2], bAH[4], bAL[4];
#pragma unroll
    for (int am = 0; am < 2; am++) {
        int r = warpM * 32 + am * 16 + (lane & 15);
        int c = (lane >> 4) * 4;
        aAH[am] = smem_u32(&sAh[r * SROW + c]);
        aAL[am] = smem_u32(&sAl[r * SROW + c]);
    }
#pragma unroll
    for (int p = 0; p < 4; p++) {
        int quad = lane >> 3;
        int rowo = ((quad == 0 || quad == 1) ? 0 : 8) + (lane & 7);
        int c = (quad & 1) * 4;
        int n = warpN * 64 + p * 16 + rowo;
        bAH[p] = smem_u32(&sBh[n * SROW + c]);
        bAL[p] = smem_u32(&sBl[n * SROW + c]);
    }

    float acc[2][8][4];
#pragma unroll
    for (int i = 0; i < 2; i++)
#pragma unroll
        for (int j = 0; j < 8; j++)
#pragma unroll
            for (int q = 0; q < 4; q++) acc[i][j][q] = 0.f;

    int lr = tid >> 1;
    int lh = (tid & 1) * 8;
    const float* aSrc = enc + (tileBase + lr) * (size_t)H_ + lh;
    const uint4* bSrcH = (const uint4*)(g_awh + (size_t)lr * 128 + lh);
    const uint4* bSrcL = (const uint4*)(g_awl + (size_t)lr * 128 + lh);
    uint32_t* aDstH = &sAh[lr * SROW + (lh >> 1)];
    uint32_t* aDstL = &sAl[lr * SROW + (lh >> 1)];
    uint32_t* bDstH = &sBh[lr * SROW + (lh >> 1)];
    uint32_t* bDstL = &sBl[lr * SROW + (lh >> 1)];

    float dpw = 0.f;

    float4 pv0 = ((const float4*)aSrc)[0];
    float4 pv1 = ((const float4*)aSrc)[1];
    uint4 pbh = bSrcH[0], pbl = bSrcL[0];

    const int nch = H_ / 16;  // 8
    for (int kc = 0; kc < nch; kc++) {
        {
            float vv[8] = {pv0.x, pv0.y, pv0.z, pv0.w, pv1.x, pv1.y, pv1.z, pv1.w};
            // dpw partial (fp32 exact)
            const float4* pwp = (const float4*)(proj_w + 128 + kc * 16 + lh);
            float4 w0 = __ldg(pwp), w1 = __ldg(pwp + 1);
            dpw += vv[0] * w0.x + vv[1] * w0.y + vv[2] * w0.z + vv[3] * w0.w
                 + vv[4] * w1.x + vv[5] * w1.y + vv[6] * w1.z + vv[7] * w1.w;
            uint32_t hh[4], ll[4];
#pragma unroll
            for (int i = 0; i < 4; i++) {
                float x = vv[2 * i], y = vv[2 * i + 1];
                __nv_bfloat162 hp = __floats2bfloat162_rn(x, y);
                float lx = x - __bfloat162float(hp.x);
                float ly = y - __bfloat162float(hp.y);
                __nv_bfloat162 lp = __floats2bfloat162_rn(lx, ly);
                hh[i] = *(uint32_t*)&hp;
                ll[i] = *(uint32_t*)&lp;
            }
            *(uint4*)aDstH = make_uint4(hh[0], hh[1], hh[2], hh[3]);
            *(uint4*)aDstL = make_uint4(ll[0], ll[1], ll[2], ll[3]);
            *(uint4*)bDstH = pbh;
            *(uint4*)bDstL = pbl;
        }
        __syncthreads();
        if (kc + 1 < nch) {
            const float4* s = (const float4*)(aSrc + (kc + 1) * 16);
            pv0 = s[0]; pv1 = s[1];
            pbh = bSrcH[(kc + 1) * 2];
            pbl = bSrcL[(kc + 1) * 2];
        }

        uint32_t aH[2][4], aL[2][4], bH[4][4], bL[4][4];
#pragma unroll
        for (int am = 0; am < 2; am++) { ldsm_x4(aH[am], aAH[am]); ldsm_x4(aL[am], aAL[am]); }
#pragma unroll
        for (int p = 0; p < 4; p++)   { ldsm_x4(bH[p], bAH[p]);   ldsm_x4(bL[p], bAL[p]); }

#pragma unroll
        for (int am = 0; am < 2; am++) {
#pragma unroll
            for (int p = 0; p < 4; p++) {
                mma_bf16(acc[am][2 * p],     aH[am], &bH[p][0]);
                mma_bf16(acc[am][2 * p],     aL[am], &bH[p][0]);
                mma_bf16(acc[am][2 * p],     aH[am], &bL[p][0]);
                mma_bf16(acc[am][2 * p + 1], aH[am], &bH[p][2]);
                mma_bf16(acc[am][2 * p + 1], aL[am], &bH[p][2]);
                mma_bf16(acc[am][2 * p + 1], aH[am], &bL[p][2]);
            }
        }
        __syncthreads();
    }

    // dpw: combine the two half-row threads and write
    {
        float d2 = dpw + __shfl_xor_sync(0xffffffffu, dpw, 1);
        if ((tid & 1) == 0) g_dpw[tileBase + lr] = d2;
    }

    // epilogue: tanh(+b) * hout, reduce over 128 cols
    float ev[2][2] = {{0.f, 0.f}, {0.f, 0.f}};
#pragma unroll
    for (int am = 0; am < 2; am++) {
        size_t gr0 = tileBase + warpM * 32 + am * 16 + (lane >> 2);
        size_t gr1 = gr0 + 8;
        const float* h0p = hout + (size_t)(gr0 & (BN - 1)) * H_;
        const float* h1p = hout + (size_t)(gr1 & (BN - 1)) * H_;
#pragma unroll
        for (int bn = 0; bn < 8; bn++) {
            int col = warpN * 64 + bn * 8 + (lane & 3) * 2;
            float2 bb = *(const float2*)(attn_b + col);
            float2 h0 = *(const float2*)(h0p + col);
            float2 h1 = *(const float2*)(h1p + col);
            ev[am][0] += tanhf(acc[am][bn][0] + bb.x) * h0.x
                       + tanhf(acc[am][bn][1] + bb.y) * h0.y;
            ev[am][1] += tanhf(acc[am][bn][2] + bb.x) * h1.x
                       + tanhf(acc[am][bn][3] + bb.y) * h1.y;
        }
    }
#pragma unroll
    for (int am = 0; am < 2; am++)
#pragma unroll
        for (int rp = 0; rp < 2; rp++) {
            ev[am][rp] += __shfl_xor_sync(0xffffffffu, ev[am][rp], 1);
            ev[am][rp] += __shfl_xor_sync(0xffffffffu, ev[am][rp], 2);
        }
    if (warpN == 1 && (lane & 3) == 0) {
#pragma unroll
        for (int am = 0; am < 2; am++)
#pragma unroll
            for (int rp = 0; rp < 2; rp++)
                sred[warpM][am][rp][lane >> 2] = ev[am][rp];
    }
    __syncthreads();
    if (warpN == 0 && (lane & 3) == 0) {
#pragma unroll
        for (int am = 0; am < 2; am++)
#pragma unroll
            for (int rp = 0; rp < 2; rp++) {
                size_t gr = tileBase + warpM * 32 + am * 16 + rp * 8 + (lane >> 2);
                g_energy[gr] = ev[am][rp] + sred[warpM][am][rp][lane >> 2];
            }
    }
}

// ---------------- softmax over S + attw + final projection -----------------
__global__ void softmax_out_kernel(const float* __restrict__ proj_w,
                                   const float* __restrict__ proj_b,
                                   const float* __restrict__ hout,
                                   float* __restrict__ out0,
                                   float* __restrict__ attw) {
    int gwarp = (blockIdx.x * blockDim.x + threadIdx.x) >> 5;
    int lane = threadIdx.x & 31;
    if (gwarp >= BN) return;
    int bn = gwarp;

    float e = (lane < S_) ? g_energy[lane * BN + bn] : -1e30f;
    float m = e;
#pragma unroll
    for (int off = 16; off > 0; off >>= 1)
        m = fmaxf(m, __shfl_xor_sync(0xffffffffu, m, off));
    float p = (lane < S_) ? expf(e - m) : 0.f;
    float s = p;
#pragma unroll
    for (int off = 16; off > 0; off >>= 1)
        s += __shfl_xor_sync(0xffffffffu, s, off);
    float a = p / s;
    if (lane < S_) attw[(size_t)bn * S_ + lane] = a;

    float acc = (lane < S_) ? a * g_dpw[lane * BN + bn] : 0.f;
#pragma unroll
    for (int j = 0; j < 4; j++) {
        int col = lane + j * 32;
        acc += hout[(size_t)bn * H_ + col] * proj_w[col];
    }
#pragma unroll
    for (int off = 16; off > 0; off >>= 1)
        acc += __shfl_xor_sync(0xffffffffu, acc, off);
    if (lane == 0) out0[bn] = acc + proj_b[0];
}

// ---------------- orchestration: kernel launches ONLY ----------------------
extern "C" void kernel_launch(void* const* d_in, const int* in_sizes, int n_in,
                              void* d_out, int out_size) {
    const float* inputs  = (const float*)d_in[0];
    const float* enc     = (const float*)d_in[1];
    const float* hidden  = (const float*)d_in[2];
    const float* cell    = (const float*)d_in[3];
    const float* sup     = (const float*)d_in[4];
    const float* w0      = (const float*)d_in[5];
    const float* b0      = (const float*)d_in[6];
    const float* w1      = (const float*)d_in[7];
    const float* b1      = (const float*)d_in[8];
    const float* attn_w  = (const float*)d_in[9];
    const float* attn_b  = (const float*)d_in[10];
    const float* proj_w  = (const float*)d_in[11];
    const float* proj_b  = (const float*)d_in[12];
    float* out = (float*)d_out;

    float* hs0 = out + HS_OFF;
    float* hs1 = out + HS_OFF + (size_t)BN * H_;
    float* cs0 = out + CS_OFF;
    float* cs1 = out + CS_OFF + (size_t)BN * H_;
    float* attw = out + ATT_OFF;

    // sparse structure + weight splits
    build_csr_kernel<<<(N_ + 255) / 256, 256>>>(sup);
    wsplit_kernel<<<(512 * K0_LDA + 255) / 256, 256>>>(w0, K0_LDA, 0);
    wsplit_kernel<<<(512 * K1_LDA + 255) / 256, 256>>>(w1, K1_LDA, 1);
    awsplit_kernel<<<(128 * 128 + 255) / 256, 256>>>(attn_w);

    // ---- layer 0 ----
    fill_x0_l0_kernel<<<(BN * 129 + 255) / 256, 256>>>(inputs, hidden);
    zero_pad_l0_kernel<<<(BN * 64 + 255) / 256, 256>>>();
    spmmv_kernel<<<dim3(N_, B_ / 4), 128>>>(K0_LDA, 0, 132, -1, 132, 0);
    spmmv_kernel<<<dim3(N_, B_ / 4), 128>>>(K0_LDA, 132, 264, 0, 132, 1);
    gates_mma_kernel<<<dim3(BN / 128, 4), 256>>>(b0, K0_LDA, K0_LDA / 16, 0);
    lstm_kernel<<<(BN * H_ + 255) / 256, 256>>>(cell, hs0, cs0);

    // ---- layer 1 ----
    fill_x0_l1_kernel<<<(BN * 256 + 255) / 256, 256>>>(hs0, hidden + (size_t)BN * H_);
    spmmv_kernel<<<dim3(N_, B_ / 4), 128>>>(K1_LDA, 0, 256, -1, 256, 0);
    spmmv_kernel<<<dim3(N_, B_ / 4), 128>>>(K1_LDA, 256, 512, 0, 256, 1);
    gates_mma_kernel<<<dim3(BN / 128, 4), 256>>>(b1, K1_LDA, K1_LDA / 16, 1);
    lstm_kernel<<<(BN * H_ + 255) / 256, 256>>>(cell + (size_t)BN * H_, hs1, cs1);

    // ---- attention + projection ----
    energy_mma_kernel<<<(S_ * BN) / 128, 256>>>(enc, attn_b, proj_w, hs1);
    softmax_out_kernel<<<BN / 8, 256>>>(proj_w, proj_b, hs1, out, attw);
}

// round 7
// speedup vs baseline: 2.2496x; 1.0305x over previous
#include <cuda_runtime.h>
#include <cuda_bf16.h>
#include <cstdint>

#define B_   64
#define N_   1024
#define BN   65536
#define H_   128
#define S_   12
#define CSR_CAP 512

#define NGATE   512
#define K0_LDA  448      // layer0: seg[h(128),x(1),pad(3)] @0,132,264; tail 396..447 zero
#define K1_LDA  768      // layer1: x0@0(256: h_new|h1) x1@256 x2@512

// d_out layout: [output 65536][hs 2*BN*H][cs 2*BN*H][attw BN*S]
#define HS_OFF   65536
#define CS_OFF   (65536 + 2 * BN * H_)
#define ATT_OFF  (CS_OFF + 2 * BN * H_)

// ---------------- scratch (device globals; no allocation allowed) ----------
__device__ float g_feats [(size_t)BN * K0_LDA];   // layer0 feats
__device__ float g_feats2[(size_t)BN * K1_LDA];   // layer1 feats
__device__ float g_energy[S_ * BN];
__device__ float g_dpw[S_ * BN];
__device__ int   g_csr_cnt[N_];
__device__ int   g_csr_col[(size_t)N_ * CSR_CAP];
__device__ float g_csr_val[(size_t)N_ * CSR_CAP];
__device__ __nv_bfloat16 g_wt0h[(size_t)512 * K0_LDA];
__device__ __nv_bfloat16 g_wt0l[(size_t)512 * K0_LDA];
__device__ __nv_bfloat16 g_wt1h[(size_t)512 * K1_LDA];
__device__ __nv_bfloat16 g_wt1l[(size_t)512 * K1_LDA];
__device__ __nv_bfloat16 g_awh[(size_t)128 * 128];   // attn_w^T hi
__device__ __nv_bfloat16 g_awl[(size_t)128 * 128];   // attn_w^T lo

__device__ __forceinline__ float sigmoidf_(float x) { return 1.f / (1.f + expf(-x)); }

__device__ __forceinline__ uint32_t smem_u32(const void* p) {
    uint32_t a;
    asm("{ .reg .u64 t; cvta.to.shared.u64 t, %1; cvt.u32.u64 %0, t; }"
        : "=r"(a) : "l"(p));
    return a;
}
__device__ __forceinline__ void ldsm_x4(uint32_t* r, uint32_t addr) {
    asm volatile("ldmatrix.sync.aligned.m8n8.x4.shared.b16 {%0,%1,%2,%3}, [%4];"
                 : "=r"(r[0]), "=r"(r[1]), "=r"(r[2]), "=r"(r[3]) : "r"(addr));
}
__device__ __forceinline__ void mma_bf16(float* d, const uint32_t* a,
                                         const uint32_t* b) {
    asm volatile(
        "mma.sync.aligned.m16n8k16.row.col.f32.bf16.bf16.f32 "
        "{%0,%1,%2,%3}, {%4,%5,%6,%7}, {%8,%9}, {%0,%1,%2,%3};"
        : "+f"(d[0]), "+f"(d[1]), "+f"(d[2]), "+f"(d[3])
        : "r"(a[0]), "r"(a[1]), "r"(a[2]), "r"(a[3]), "r"(b[0]), "r"(b[1]));
}

// ---------------- CSR build (warp-ballot compaction, order-preserving) -----
__global__ void build_csr_kernel(const float* __restrict__ sup) {
    int n = blockIdx.x * (blockDim.x >> 5) + (threadIdx.x >> 5);
    int lane = threadIdx.x & 31;
    if (n >= N_) return;
    const float* row = sup + (size_t)n * N_;
    int cnt = 0;
    for (int base = 0; base < N_; base += 32) {
        float v = row[base + lane];
        unsigned mask = __ballot_sync(0xffffffffu, v != 0.f);
        if (v != 0.f) {
            int pos = cnt + __popc(mask & ((1u << lane) - 1u));
            if (pos < CSR_CAP) {
                g_csr_col[n * CSR_CAP + pos] = base + lane;
                g_csr_val[n * CSR_CAP + pos] = v;
            }
        }
        cnt += __popc(mask);
    }
    if (lane == 0) g_csr_cnt[n] = cnt < CSR_CAP ? cnt : CSR_CAP;
}

// ---------------- W split: gate-interleaved cols, permuted k rows ----------
// output col n_il: h = n_il>>2, gate = n_il&3 -> orig n = gate*128 + h
// layer0 k perm: seg=k/132, p=k%132: p<128 -> orig f=p+1 ; p==128 -> f=0 ; else pad
__global__ void wsplit_kernel(const float* __restrict__ w, int Kpad, int layer) {
    int t = blockIdx.x * blockDim.x + threadIdx.x;
    if (t >= 512 * Kpad) return;
    int n_il = t / Kpad, k = t - n_il * Kpad;
    int n = (n_il & 3) * 128 + (n_il >> 2);
    int r = -1;
    if (layer == 0) {
        if (k < 396) {
            int seg = k / 132, p = k - seg * 132;
            int f = (p < 128) ? p + 1 : (p == 128 ? 0 : -1);
            if (f >= 0) r = seg * 129 + f;
        }
    } else {
        if (k < 768) r = k;
    }
    float v = (r >= 0) ? w[(size_t)r * NGATE + n] : 0.f;
    __nv_bfloat16 h = __float2bfloat16(v);
    __nv_bfloat16 l = __float2bfloat16(v - __bfloat162float(h));
    if (layer == 0) { g_wt0h[t] = h; g_wt0l[t] = l; }
    else            { g_wt1h[t] = h; g_wt1l[t] = l; }
}

// attn_w [k=128][n=128] -> transposed hi/lo [n][k] (no interleave)
__global__ void awsplit_kernel(const float* __restrict__ aw) {
    int t = blockIdx.x * blockDim.x + threadIdx.x;
    if (t >= 128 * 128) return;
    int n = t >> 7, k = t & 127;
    float v = aw[k * 128 + n];
    __nv_bfloat16 h = __float2bfloat16(v);
    __nv_bfloat16 l = __float2bfloat16(v - __bfloat162float(h));
    g_awh[t] = h;
    g_awl[t] = l;
}

// ---------------- fill layer0 x0: cols 0..127 = h0 (vec), 128 = input ------
__global__ void fill_x0_l0_kernel(const float* __restrict__ inputs,
                                  const float* __restrict__ h0) {
    int t = blockIdx.x * blockDim.x + threadIdx.x;
    if (t >= BN * 33) return;
    int r = t / 33, u = t - r * 33;
    float* dst = g_feats + (size_t)r * K0_LDA;
    if (u < 32) {
        ((float4*)dst)[u] = ((const float4*)(h0 + (size_t)r * H_))[u];
    } else {
        dst[128] = inputs[r];
        dst[129] = 0.f; dst[130] = 0.f; dst[131] = 0.f;
    }
}

// ---------------- fill layer1 h1 part (cols 128..255 of g_feats2) ----------
__global__ void fill_h1_kernel(const float* __restrict__ h1) {
    int t = blockIdx.x * blockDim.x + threadIdx.x;
    if (t >= BN * 32) return;
    int r = t >> 5, u = t & 31;
    ((float4*)(g_feats2 + (size_t)r * K1_LDA + 128))[u] =
        ((const float4*)(h1 + (size_t)r * H_))[u];
}

// ---------------- vectorized sparse diffusion ------------------------------
__global__ __launch_bounds__(128) void spmmv_kernel(int buf, int ld, int srcCol,
                                                    int dstCol, int prevCol,
                                                    int D4, int cheb) {
    __shared__ int   scol[CSR_CAP];
    __shared__ float sval[CSR_CAP];
    float* F = buf ? g_feats2 : g_feats;
    int n = blockIdx.x;
    int tid = threadIdx.x, bq = tid >> 5, tq = tid & 31;
    int cnt = g_csr_cnt[n];
    for (int i = tid; i < cnt; i += 128) {
        scol[i] = g_csr_col[n * CSR_CAP + i];
        sval[i] = g_csr_val[n * CSR_CAP + i];
    }
    __syncthreads();
    int b = blockIdx.y * 4 + bq;
    const float* srcB = F + (size_t)b * N_ * ld + srcCol;
    size_t rbase = ((size_t)b * N_ + n) * ld;
    for (int d0 = tq * 4; d0 < D4; d0 += 128) {
        float4 acc = make_float4(0.f, 0.f, 0.f, 0.f);
        for (int i = 0; i < cnt; i++) {
            const float4 v = *(const float4*)(srcB + (size_t)scol[i] * ld + d0);
            float s = sval[i];
            acc.x += s * v.x; acc.y += s * v.y; acc.z += s * v.z; acc.w += s * v.w;
        }
        if (cheb) {
            float4 p = *(const float4*)(F + rbase + prevCol + d0);
            acc.x = 2.f * acc.x - p.x; acc.y = 2.f * acc.y - p.y;
            acc.z = 2.f * acc.z - p.z; acc.w = 2.f * acc.w - p.w;
        }
        *(float4*)(F + rbase + dstCol + d0) = acc;
    }
}

// ---------------- gates GEMM + fused LSTM ----------------------------------
// acc = feats @ W_interleaved (3-product bf16 split); epilogue does the LSTM
// pointwise via lane-pair shuffles and writes h,c directly (no gates buffer).
#define SROW 12   // smem row stride in uint32 (24 bf16 = 48 B)
__global__ __launch_bounds__(256) void gates_mma_kernel(
    const float* __restrict__ bias, const float* __restrict__ c_in,
    float* __restrict__ h_out, float* __restrict__ c_out,
    int lda, int nch, int layer) {
    __shared__ __align__(16) uint32_t sAh[128 * SROW];
    __shared__ __align__(16) uint32_t sAl[128 * SROW];
    __shared__ __align__(16) uint32_t sBh[128 * SROW];
    __shared__ __align__(16) uint32_t sBl[128 * SROW];

    const float* F = layer ? g_feats2 : g_feats;
    const __nv_bfloat16* wt_hi = layer ? g_wt1h : g_wt0h;
    const __nv_bfloat16* wt_lo = layer ? g_wt1l : g_wt0l;

    int tid = threadIdx.x, lane = tid & 31, wid = tid >> 5;
    int warpM = wid & 3, warpN = wid >> 2;
    int colBase = blockIdx.x * 128;                  // col fastest: A reuse in L2
    size_t rowBase = (size_t)blockIdx.y * 128;

    uint32_t aAH[2], aAL[2], bAH[4], bAL[4];
#pragma unroll
    for (int am = 0; am < 2; am++) {
        int r = warpM * 32 + am * 16 + (lane & 15);
        int c = (lane >> 4) * 4;
        aAH[am] = smem_u32(&sAh[r * SROW + c]);
        aAL[am] = smem_u32(&sAl[r * SROW + c]);
    }
#pragma unroll
    for (int p = 0; p < 4; p++) {
        int quad = lane >> 3;
        int rowo = ((quad == 0 || quad == 1) ? 0 : 8) + (lane & 7);
        int c = (quad & 1) * 4;
        int n = warpN * 64 + p * 16 + rowo;
        bAH[p] = smem_u32(&sBh[n * SROW + c]);
        bAL[p] = smem_u32(&sBl[n * SROW + c]);
    }

    float acc[2][8][4];
#pragma unroll
    for (int i = 0; i < 2; i++)
#pragma unroll
        for (int j = 0; j < 8; j++)
#pragma unroll
            for (int q = 0; q < 4; q++) acc[i][j][q] = 0.f;

    int lr = tid >> 1;
    int lh = (tid & 1) * 8;
    const float* aSrc = F + (rowBase + lr) * (size_t)lda + lh;
    const uint4* bSrcH = (const uint4*)(wt_hi + (size_t)(colBase + lr) * lda + lh);
    const uint4* bSrcL = (const uint4*)(wt_lo + (size_t)(colBase + lr) * lda + lh);
    uint32_t* aDstH = &sAh[lr * SROW + (lh >> 1)];
    uint32_t* aDstL = &sAl[lr * SROW + (lh >> 1)];
    uint32_t* bDstH = &sBh[lr * SROW + (lh >> 1)];
    uint32_t* bDstL = &sBl[lr * SROW + (lh >> 1)];

    float4 pv0 = ((const float4*)aSrc)[0];
    float4 pv1 = ((const float4*)aSrc)[1];
    uint4 pbh = bSrcH[0], pbl = bSrcL[0];

    for (int kc = 0; kc < nch; kc++) {
        {
            float vv[8] = {pv0.x, pv0.y, pv0.z, pv0.w, pv1.x, pv1.y, pv1.z, pv1.w};
            uint32_t hh[4], ll[4];
#pragma unroll
            for (int i = 0; i < 4; i++) {
                float x = vv[2 * i], y = vv[2 * i + 1];
                __nv_bfloat162 hp = __floats2bfloat162_rn(x, y);
                float lx = x - __bfloat162float(hp.x);
                float ly = y - __bfloat162float(hp.y);
                __nv_bfloat162 lp = __floats2bfloat162_rn(lx, ly);
                hh[i] = *(uint32_t*)&hp;
                ll[i] = *(uint32_t*)&lp;
            }
            *(uint4*)aDstH = make_uint4(hh[0], hh[1], hh[2], hh[3]);
            *(uint4*)aDstL = make_uint4(ll[0], ll[1], ll[2], ll[3]);
            *(uint4*)bDstH = pbh;
            *(uint4*)bDstL = pbl;
        }
        __syncthreads();
        if (kc + 1 < nch) {
            const float4* s = (const float4*)(aSrc + (kc + 1) * 16);
            pv0 = s[0]; pv1 = s[1];
            pbh = bSrcH[(kc + 1) * 2];
            pbl = bSrcL[(kc + 1) * 2];
        }

        uint32_t aH[2][4], aL[2][4], bH[4][4], bL[4][4];
#pragma unroll
        for (int am = 0; am < 2; am++) { ldsm_x4(aH[am], aAH[am]); ldsm_x4(aL[am], aAL[am]); }
#pragma unroll
        for (int p = 0; p < 4; p++)   { ldsm_x4(bH[p], bAH[p]);   ldsm_x4(bL[p], bAL[p]); }

#pragma unroll
        for (int am = 0; am < 2; am++) {
#pragma unroll
            for (int p = 0; p < 4; p++) {
                mma_bf16(acc[am][2 * p],     aH[am], &bH[p][0]);
                mma_bf16(acc[am][2 * p],     aL[am], &bH[p][0]);
                mma_bf16(acc[am][2 * p],     aH[am], &bL[p][0]);
                mma_bf16(acc[am][2 * p + 1], aH[am], &bH[p][2]);
                mma_bf16(acc[am][2 * p + 1], aL[am], &bH[p][2]);
                mma_bf16(acc[am][2 * p + 1], aH[am], &bL[p][2]);
            }
        }
        __syncthreads();
    }

    // ---- fused LSTM epilogue ----
    // col c = 4h+g. lane-pair (lane^1): even holds (i,f), odd holds (o,g).
    int evenp = (lane & 1) == 0;
#pragma unroll
    for (int am = 0; am < 2; am++) {
#pragma unroll
        for (int rp = 0; rp < 2; rp++) {
            size_t row = rowBase + warpM * 32 + am * 16 + rp * 8 + (lane >> 2);
#pragma unroll
            for (int bn = 0; bn < 8; bn++) {
                int cbase = colBase + warpN * 64 + bn * 8 + (lane & 3) * 2;
                int h = cbase >> 2;
                float a0 = acc[am][bn][rp * 2 + 0];
                float a1 = acc[am][bn][rp * 2 + 1];
                float v0, v1;
                if (evenp) {
                    v0 = sigmoidf_(a0 + __ldg(bias + h));          // i
                    v1 = sigmoidf_(a1 + __ldg(bias + 128 + h));    // f
                } else {
                    v0 = sigmoidf_(a0 + __ldg(bias + 256 + h));    // o
                    v1 = tanhf(a1 + __ldg(bias + 384 + h));        // g
                }
                float ex = __shfl_xor_sync(0xffffffffu, v1, 1);    // even<-g, odd<-f
                float tn = 0.f;
                if (evenp) {
                    float cin = c_in[row * H_ + h];
                    float cn = v1 * cin + v0 * ex;                 // f*c + i*g
                    c_out[row * H_ + h] = cn;
                    tn = tanhf(cn);
                }
                float t2 = __shfl_xor_sync(0xffffffffu, tn, 1);    // odd<-tanh(cn)
                if (!evenp) {
                    float hv = v0 * t2;                            // o*tanh(cn)
                    h_out[row * H_ + h] = hv;
                    if (layer == 0)
                        g_feats2[row * (size_t)K1_LDA + h] = hv;
                }
            }
        }
    }
}

// ---------------- mma-based attention energy + dpw, one pass over enc ------
__global__ __launch_bounds__(256) void energy_mma_kernel(
    const float* __restrict__ enc, const float* __restrict__ attn_b,
    const float* __restrict__ proj_w, const float* __restrict__ hout) {
    __shared__ __align__(16) uint32_t sAh[128 * SROW];
    __shared__ __align__(16) uint32_t sAl[128 * SROW];
    __shared__ __align__(16) uint32_t sBh[128 * SROW];
    __shared__ __align__(16) uint32_t sBl[128 * SROW];
    __shared__ float sred[4][2][2][8];

    int tid = threadIdx.x, lane = tid & 31, wid = tid >> 5;
    int warpM = wid & 3, warpN = wid >> 2;
    size_t tileBase = (size_t)blockIdx.x * 128;

    uint32_t aAH[2], aAL[2], bAH[4], bAL[4];
#pragma unroll
    for (int am = 0; am < 2; am++) {
        int r = warpM * 32 + am * 16 + (lane & 15);
        int c = (lane >> 4) * 4;
        aAH[am] = smem_u32(&sAh[r * SROW + c]);
        aAL[am] = smem_u32(&sAl[r * SROW + c]);
    }
#pragma unroll
    for (int p = 0; p < 4; p++) {
        int quad = lane >> 3;
        int rowo = ((quad == 0 || quad == 1) ? 0 : 8) + (lane & 7);
        int c = (quad & 1) * 4;
        int n = warpN * 64 + p * 16 + rowo;
        bAH[p] = smem_u32(&sBh[n * SROW + c]);
        bAL[p] = smem_u32(&sBl[n * SROW + c]);
    }

    float acc[2][8][4];
#pragma unroll
    for (int i = 0; i < 2; i++)
#pragma unroll
        for (int j = 0; j < 8; j++)
#pragma unroll
            for (int q = 0; q < 4; q++) acc[i][j][q] = 0.f;

    int lr = tid >> 1;
    int lh = (tid & 1) * 8;
    const float* aSrc = enc + (tileBase + lr) * (size_t)H_ + lh;
    const uint4* bSrcH = (const uint4*)(g_awh + (size_t)lr * 128 + lh);
    const uint4* bSrcL = (const uint4*)(g_awl + (size_t)lr * 128 + lh);
    uint32_t* aDstH = &sAh[lr * SROW + (lh >> 1)];
    uint32_t* aDstL = &sAl[lr * SROW + (lh >> 1)];
    uint32_t* bDstH = &sBh[lr * SROW + (lh >> 1)];
    uint32_t* bDstL = &sBl[lr * SROW + (lh >> 1)];

    float dpw = 0.f;

    float4 pv0 = ((const float4*)aSrc)[0];
    float4 pv1 = ((const float4*)aSrc)[1];
    uint4 pbh = bSrcH[0], pbl = bSrcL[0];

    const int nch = H_ / 16;  // 8
    for (int kc = 0; kc < nch; kc++) {
        {
            float vv[8] = {pv0.x, pv0.y, pv0.z, pv0.w, pv1.x, pv1.y, pv1.z, pv1.w};
            const float4* pwp = (const float4*)(proj_w + 128 + kc * 16 + lh);
            float4 w0 = __ldg(pwp), w1 = __ldg(pwp + 1);
            dpw += vv[0] * w0.x + vv[1] * w0.y + vv[2] * w0.z + vv[3] * w0.w
                 + vv[4] * w1.x + vv[5] * w1.y + vv[6] * w1.z + vv[7] * w1.w;
            uint32_t hh[4], ll[4];
#pragma unroll
            for (int i = 0; i < 4; i++) {
                float x = vv[2 * i], y = vv[2 * i + 1];
                __nv_bfloat162 hp = __floats2bfloat162_rn(x, y);
                float lx = x - __bfloat162float(hp.x);
                float ly = y - __bfloat162float(hp.y);
                __nv_bfloat162 lp = __floats2bfloat162_rn(lx, ly);
                hh[i] = *(uint32_t*)&hp;
                ll[i] = *(uint32_t*)&lp;
            }
            *(uint4*)aDstH = make_uint4(hh[0], hh[1], hh[2], hh[3]);
            *(uint4*)aDstL = make_uint4(ll[0], ll[1], ll[2], ll[3]);
            *(uint4*)bDstH = pbh;
            *(uint4*)bDstL = pbl;
        }
        __syncthreads();
        if (kc + 1 < nch) {
            const float4* s = (const float4*)(aSrc + (kc + 1) * 16);
            pv0 = s[0]; pv1 = s[1];
            pbh = bSrcH[(kc + 1) * 2];
            pbl = bSrcL[(kc + 1) * 2];
        }

        uint32_t aH[2][4], aL[2][4], bH[4][4], bL[4][4];
#pragma unroll
        for (int am = 0; am < 2; am++) { ldsm_x4(aH[am], aAH[am]); ldsm_x4(aL[am], aAL[am]); }
#pragma unroll
        for (int p = 0; p < 4; p++)   { ldsm_x4(bH[p], bAH[p]);   ldsm_x4(bL[p], bAL[p]); }

#pragma unroll
        for (int am = 0; am < 2; am++) {
#pragma unroll
            for (int p = 0; p < 4; p++) {
                mma_bf16(acc[am][2 * p],     aH[am], &bH[p][0]);
                mma_bf16(acc[am][2 * p],     aL[am], &bH[p][0]);
                mma_bf16(acc[am][2 * p],     aH[am], &bL[p][0]);
                mma_bf16(acc[am][2 * p + 1], aH[am], &bH[p][2]);
                mma_bf16(acc[am][2 * p + 1], aL[am], &bH[p][2]);
                mma_bf16(acc[am][2 * p + 1], aH[am], &bL[p][2]);
            }
        }
        __syncthreads();
    }

    {
        float d2 = dpw + __shfl_xor_sync(0xffffffffu, dpw, 1);
        if ((tid & 1) == 0) g_dpw[tileBase + lr] = d2;
    }

    float ev[2][2] = {{0.f, 0.f}, {0.f, 0.f}};
#pragma unroll
    for (int am = 0; am < 2; am++) {
        size_t gr0 = tileBase + warpM * 32 + am * 16 + (lane >> 2);
        size_t gr1 = gr0 + 8;
        const float* h0p = hout + (size_t)(gr0 & (BN - 1)) * H_;
        const float* h1p = hout + (size_t)(gr1 & (BN - 1)) * H_;
#pragma unroll
        for (int bn = 0; bn < 8; bn++) {
            int col = warpN * 64 + bn * 8 + (lane & 3) * 2;
            float2 bb = *(const float2*)(attn_b + col);
            float2 h0 = *(const float2*)(h0p + col);
            float2 h1 = *(const float2*)(h1p + col);
            ev[am][0] += tanhf(acc[am][bn][0] + bb.x) * h0.x
                       + tanhf(acc[am][bn][1] + bb.y) * h0.y;
            ev[am][1] += tanhf(acc[am][bn][2] + bb.x) * h1.x
                       + tanhf(acc[am][bn][3] + bb.y) * h1.y;
        }
    }
#pragma unroll
    for (int am = 0; am < 2; am++)
#pragma unroll
        for (int rp = 0; rp < 2; rp++) {
            ev[am][rp] += __shfl_xor_sync(0xffffffffu, ev[am][rp], 1);
            ev[am][rp] += __shfl_xor_sync(0xffffffffu, ev[am][rp], 2);
        }
    if (warpN == 1 && (lane & 3) == 0) {
#pragma unroll
        for (int am = 0; am < 2; am++)
#pragma unroll
            for (int rp = 0; rp < 2; rp++)
                sred[warpM][am][rp][lane >> 2] = ev[am][rp];
    }
    __syncthreads();
    if (warpN == 0 && (lane & 3) == 0) {
#pragma unroll
        for (int am = 0; am < 2; am++)
#pragma unroll
            for (int rp = 0; rp < 2; rp++) {
                size_t gr = tileBase + warpM * 32 + am * 16 + rp * 8 + (lane >> 2);
                g_energy[gr] = ev[am][rp] + sred[warpM][am][rp][lane >> 2];
            }
    }
}

// ---------------- softmax over S + attw + final projection -----------------
__global__ void softmax_out_kernel(const float* __restrict__ proj_w,
                                   const float* __restrict__ proj_b,
                                   const float* __restrict__ hout,
                                   float* __restrict__ out0,
                                   float* __restrict__ attw) {
    int gwarp = (blockIdx.x * blockDim.x + threadIdx.x) >> 5;
    int lane = threadIdx.x & 31;
    if (gwarp >= BN) return;
    int bn = gwarp;

    float e = (lane < S_) ? g_energy[lane * BN + bn] : -1e30f;
    float m = e;
#pragma unroll
    for (int off = 16; off > 0; off >>= 1)
        m = fmaxf(m, __shfl_xor_sync(0xffffffffu, m, off));
    float p = (lane < S_) ? expf(e - m) : 0.f;
    float s = p;
#pragma unroll
    for (int off = 16; off > 0; off >>= 1)
        s += __shfl_xor_sync(0xffffffffu, s, off);
    float a = p / s;
    if (lane < S_) attw[(size_t)bn * S_ + lane] = a;

    float acc = (lane < S_) ? a * g_dpw[lane * BN + bn] : 0.f;
#pragma unroll
    for (int j = 0; j < 4; j++) {
        int col = lane + j * 32;
        acc += hout[(size_t)bn * H_ + col] * proj_w[col];
    }
#pragma unroll
    for (int off = 16; off > 0; off >>= 1)
        acc += __shfl_xor_sync(0xffffffffu, acc, off);
    if (lane == 0) out0[bn] = acc + proj_b[0];
}

// ---------------- orchestration: kernel launches ONLY ----------------------
extern "C" void kernel_launch(void* const* d_in, const int* in_sizes, int n_in,
                              void* d_out, int out_size) {
    const float* inputs  = (const float*)d_in[0];
    const float* enc     = (const float*)d_in[1];
    const float* hidden  = (const float*)d_in[2];
    const float* cell    = (const float*)d_in[3];
    const float* sup     = (const float*)d_in[4];
    const float* w0      = (const float*)d_in[5];
    const float* b0      = (const float*)d_in[6];
    const float* w1      = (const float*)d_in[7];
    const float* b1      = (const float*)d_in[8];
    const float* attn_w  = (const float*)d_in[9];
    const float* attn_b  = (const float*)d_in[10];
    const float* proj_w  = (const float*)d_in[11];
    const float* proj_b  = (const float*)d_in[12];
    float* out = (float*)d_out;

    float* hs0 = out + HS_OFF;
    float* hs1 = out + HS_OFF + (size_t)BN * H_;
    float* cs0 = out + CS_OFF;
    float* cs1 = out + CS_OFF + (size_t)BN * H_;
    float* attw = out + ATT_OFF;

    // launch index 3 = spmmv layer0 hop1 (for ncu sampling)
    build_csr_kernel<<<N_ / 8, 256>>>(sup);                                   // 0
    fill_x0_l0_kernel<<<(BN * 33 + 255) / 256, 256>>>(inputs, hidden);        // 1
    wsplit_kernel<<<(512 * K0_LDA + 255) / 256, 256>>>(w0, K0_LDA, 0);        // 2
    spmmv_kernel<<<dim3(N_, B_ / 4), 128>>>(0, K0_LDA, 0, 132, -1, 132, 0);   // 3
    spmmv_kernel<<<dim3(N_, B_ / 4), 128>>>(0, K0_LDA, 132, 264, 0, 132, 1);  // 4
    wsplit_kernel<<<(512 * K1_LDA + 255) / 256, 256>>>(w1, K1_LDA, 1);        // 5
    awsplit_kernel<<<(128 * 128 + 255) / 256, 256>>>(attn_w);                 // 6
    fill_h1_kernel<<<(BN * 32 + 255) / 256, 256>>>(hidden + (size_t)BN * H_); // 7
    gates_mma_kernel<<<dim3(4, BN / 128), 256>>>(b0, cell, hs0, cs0,
                                                 K0_LDA, K0_LDA / 16, 0);     // 8
    spmmv_kernel<<<dim3(N_, B_ / 4), 128>>>(1, K1_LDA, 0, 256, -1, 256, 0);   // 9
    spmmv_kernel<<<dim3(N_, B_ / 4), 128>>>(1, K1_LDA, 256, 512, 0, 256, 1);  // 10
    gates_mma_kernel<<<dim3(4, BN / 128), 256>>>(b1, cell + (size_t)BN * H_,
                                                 hs1, cs1,
                                                 K1_LDA, K1_LDA / 16, 1);     // 11
    energy_mma_kernel<<<(S_ * BN) / 128, 256>>>(enc, attn_b, proj_w, hs1);    // 12
    softmax_out_kernel<<<BN / 8, 256>>>(proj_w, proj_b, hs1, out, attw);      // 13
}

// round 8
// speedup vs baseline: 2.4035x; 1.0684x over previous
#include <cuda_runtime.h>
#include <cuda_bf16.h>
#include <cstdint>

#define B_   64
#define N_   1024
#define BN   65536
#define H_   128
#define S_   12
#define CSR_CAP 512

#define NGATE   512
#define K0_LDA  448      // layer0: seg[h(128),x(1),pad(3)] @0,132,264; tail 396..447 zero
#define K1_LDA  768      // layer1: x0@0(256: h_new|h1) x1@256 x2@512

// d_out layout: [output 65536][hs 2*BN*H][cs 2*BN*H][attw BN*S]
#define HS_OFF   65536
#define CS_OFF   (65536 + 2 * BN * H_)
#define ATT_OFF  (CS_OFF + 2 * BN * H_)

// ---------------- scratch (device globals; no allocation allowed) ----------
__device__ float g_feats [(size_t)BN * K0_LDA];   // layer0 feats
__device__ float g_feats2[(size_t)BN * K1_LDA];   // layer1 feats
__device__ float g_energy[S_ * BN];
__device__ float g_dpw[S_ * BN];
__device__ int   g_csr_cnt[N_];
__device__ int   g_csr_col[(size_t)N_ * CSR_CAP];
__device__ float g_csr_val[(size_t)N_ * CSR_CAP];
__device__ __nv_bfloat16 g_wt0h[(size_t)512 * K0_LDA];
__device__ __nv_bfloat16 g_wt0l[(size_t)512 * K0_LDA];
__device__ __nv_bfloat16 g_wt1h[(size_t)512 * K1_LDA];
__device__ __nv_bfloat16 g_wt1l[(size_t)512 * K1_LDA];
__device__ __nv_bfloat16 g_awh[(size_t)128 * 128];   // attn_w^T hi
__device__ __nv_bfloat16 g_awl[(size_t)128 * 128];   // attn_w^T lo

__device__ __forceinline__ float sigmoidf_(float x) { return 1.f / (1.f + expf(-x)); }

__device__ __forceinline__ uint32_t smem_u32(const void* p) {
    uint32_t a;
    asm("{ .reg .u64 t; cvta.to.shared.u64 t, %1; cvt.u32.u64 %0, t; }"
        : "=r"(a) : "l"(p));
    return a;
}
__device__ __forceinline__ void ldsm_x4(uint32_t* r, uint32_t addr) {
    asm volatile("ldmatrix.sync.aligned.m8n8.x4.shared.b16 {%0,%1,%2,%3}, [%4];"
                 : "=r"(r[0]), "=r"(r[1]), "=r"(r[2]), "=r"(r[3]) : "r"(addr));
}
__device__ __forceinline__ void mma_bf16(float* d, const uint32_t* a,
                                         const uint32_t* b) {
    asm volatile(
        "mma.sync.aligned.m16n8k16.row.col.f32.bf16.bf16.f32 "
        "{%0,%1,%2,%3}, {%4,%5,%6,%7}, {%8,%9}, {%0,%1,%2,%3};"
        : "+f"(d[0]), "+f"(d[1]), "+f"(d[2]), "+f"(d[3])
        : "r"(a[0]), "r"(a[1]), "r"(a[2]), "r"(a[3]), "r"(b[0]), "r"(b[1]));
}

// ---------------- fused setup: csr + fills + weight splits -----------------
// block ranges: [0,128) csr | [128,8576) fill_x0_l0 | [8576,9472) wsplit0
// [9472,11008) wsplit1 | [11008,11072) awsplit | [11072,19264) fill_h1
__global__ __launch_bounds__(256) void setup_kernel(
    const float* __restrict__ inputs, const float* __restrict__ h0,
    const float* __restrict__ h1, const float* __restrict__ sup,
    const float* __restrict__ w0, const float* __restrict__ w1,
    const float* __restrict__ aw) {
    int blk = blockIdx.x;
    int tid = threadIdx.x;
    if (blk < 128) {
        // CSR build, warp-ballot compaction
        int n = blk * 8 + (tid >> 5);
        int lane = tid & 31;
        const float* row = sup + (size_t)n * N_;
        int cnt = 0;
        for (int base = 0; base < N_; base += 32) {
            float v = row[base + lane];
            unsigned mask = __ballot_sync(0xffffffffu, v != 0.f);
            if (v != 0.f) {
                int pos = cnt + __popc(mask & ((1u << lane) - 1u));
                if (pos < CSR_CAP) {
                    g_csr_col[n * CSR_CAP + pos] = base + lane;
                    g_csr_val[n * CSR_CAP + pos] = v;
                }
            }
            cnt += __popc(mask);
        }
        if (lane == 0) g_csr_cnt[n] = cnt < CSR_CAP ? cnt : CSR_CAP;
    } else if (blk < 8576) {
        // fill layer0 x0: cols 0..127 = h0 (float4), 128 = input, 129..131 = 0
        int t = (blk - 128) * 256 + tid;
        if (t >= BN * 33) return;
        int r = t / 33, u = t - r * 33;
        float* dst = g_feats + (size_t)r * K0_LDA;
        if (u < 32) {
            ((float4*)dst)[u] = ((const float4*)(h0 + (size_t)r * H_))[u];
        } else {
            dst[128] = inputs[r];
            dst[129] = 0.f; dst[130] = 0.f; dst[131] = 0.f;
        }
    } else if (blk < 9472) {
        // wsplit layer0 (gate-interleaved cols, permuted k rows)
        int t = (blk - 8576) * 256 + tid;
        if (t >= 512 * K0_LDA) return;
        int n_il = t / K0_LDA, k = t - n_il * K0_LDA;
        int n = (n_il & 3) * 128 + (n_il >> 2);
        int r = -1;
        if (k < 396) {
            int seg = (k * 0x3E1) >> 17;          // k/132 for k<396
            int p = k - seg * 132;
            int f = (p < 128) ? p + 1 : (p == 128 ? 0 : -1);
            if (f >= 0) r = seg * 129 + f;
        }
        float v = (r >= 0) ? w0[(size_t)r * NGATE + n] : 0.f;
        __nv_bfloat16 h = __float2bfloat16(v);
        __nv_bfloat16 l = __float2bfloat16(v - __bfloat162float(h));
        g_wt0h[t] = h; g_wt0l[t] = l;
    } else if (blk < 11008) {
        // wsplit layer1
        int t = (blk - 9472) * 256 + tid;
        if (t >= 512 * K1_LDA) return;
        int n_il = t / K1_LDA, k = t - n_il * K1_LDA;
        int n = (n_il & 3) * 128 + (n_il >> 2);
        float v = w1[(size_t)k * NGATE + n];
        __nv_bfloat16 h = __float2bfloat16(v);
        __nv_bfloat16 l = __float2bfloat16(v - __bfloat162float(h));
        g_wt1h[t] = h; g_wt1l[t] = l;
    } else if (blk < 11072) {
        // awsplit: attn_w [k][n] -> [n][k] hi/lo
        int t = (blk - 11008) * 256 + tid;
        int n = t >> 7, k = t & 127;
        float v = aw[k * 128 + n];
        __nv_bfloat16 h = __float2bfloat16(v);
        __nv_bfloat16 l = __float2bfloat16(v - __bfloat162float(h));
        g_awh[t] = h; g_awl[t] = l;
    } else {
        // fill layer1 h1 part (cols 128..255 of g_feats2)
        int t = (blk - 11072) * 256 + tid;
        if (t >= BN * 32) return;
        int r = t >> 5, u = t & 31;
        ((float4*)(g_feats2 + (size_t)r * K1_LDA + 128))[u] =
            ((const float4*)(h1 + (size_t)r * H_))[u];
    }
}

// ---------------- vectorized sparse diffusion ------------------------------
__global__ __launch_bounds__(128) void spmmv_kernel(int buf, int ld, int srcCol,
                                                    int dstCol, int prevCol,
                                                    int D4, int cheb) {
    __shared__ int   scol[CSR_CAP];   // pre-multiplied by ld
    __shared__ float sval[CSR_CAP];
    float* F = buf ? g_feats2 : g_feats;
    int n = blockIdx.x;
    int tid = threadIdx.x, bq = tid >> 5, tq = tid & 31;
    int cnt = g_csr_cnt[n];
    for (int i = tid; i < cnt; i += 128) {
        scol[i] = g_csr_col[n * CSR_CAP + i] * ld;
        sval[i] = g_csr_val[n * CSR_CAP + i];
    }
    __syncthreads();
    int b = blockIdx.y * 4 + bq;
    const float* srcB = F + (size_t)b * N_ * ld + srcCol;
    size_t rbase = ((size_t)b * N_ + n) * ld;
    for (int d0 = tq * 4; d0 < D4; d0 += 128) {
        float4 acc = make_float4(0.f, 0.f, 0.f, 0.f);
        for (int i = 0; i < cnt; i++) {
            const float4 v = *(const float4*)(srcB + scol[i] + d0);
            float s = sval[i];
            acc.x += s * v.x; acc.y += s * v.y; acc.z += s * v.z; acc.w += s * v.w;
        }
        if (cheb) {
            float4 p = *(const float4*)(F + rbase + prevCol + d0);
            acc.x = 2.f * acc.x - p.x; acc.y = 2.f * acc.y - p.y;
            acc.z = 2.f * acc.z - p.z; acc.w = 2.f * acc.w - p.w;
        }
        *(float4*)(F + rbase + dstCol + d0) = acc;
    }
}

// ---------------- gates GEMM + fused LSTM (double-buffered smem) -----------
#define SROW 12   // smem row stride in uint32 (24 bf16 = 48 B)
#define STAGE_U32 (128 * SROW)
__global__ __launch_bounds__(256) void gates_mma_kernel(
    const float* __restrict__ bias, const float* __restrict__ c_in,
    float* __restrict__ h_out, float* __restrict__ c_out,
    int lda, int nch, int layer) {
    __shared__ __align__(16) uint32_t sAh[2][STAGE_U32];
    __shared__ __align__(16) uint32_t sAl[2][STAGE_U32];
    __shared__ __align__(16) uint32_t sBh[2][STAGE_U32];
    __shared__ __align__(16) uint32_t sBl[2][STAGE_U32];

    const float* F = layer ? g_feats2 : g_feats;
    const __nv_bfloat16* wt_hi = layer ? g_wt1h : g_wt0h;
    const __nv_bfloat16* wt_lo = layer ? g_wt1l : g_wt0l;

    int tid = threadIdx.x, lane = tid & 31, wid = tid >> 5;
    int warpM = wid & 3, warpN = wid >> 2;
    int colBase = blockIdx.x * 128;
    size_t rowBase = (size_t)blockIdx.y * 128;

    uint32_t aAH[2], aAL[2], bAH[4], bAL[4];   // stage-0 addresses
#pragma unroll
    for (int am = 0; am < 2; am++) {
        int r = warpM * 32 + am * 16 + (lane & 15);
        int c = (lane >> 4) * 4;
        aAH[am] = smem_u32(&sAh[0][r * SROW + c]);
        aAL[am] = smem_u32(&sAl[0][r * SROW + c]);
    }
#pragma unroll
    for (int p = 0; p < 4; p++) {
        int quad = lane >> 3;
        int rowo = ((quad == 0 || quad == 1) ? 0 : 8) + (lane & 7);
        int c = (quad & 1) * 4;
        int n = warpN * 64 + p * 16 + rowo;
        bAH[p] = smem_u32(&sBh[0][n * SROW + c]);
        bAL[p] = smem_u32(&sBl[0][n * SROW + c]);
    }

    float acc[2][8][4];
#pragma unroll
    for (int i = 0; i < 2; i++)
#pragma unroll
        for (int j = 0; j < 8; j++)
#pragma unroll
            for (int q = 0; q < 4; q++) acc[i][j][q] = 0.f;

    int lr = tid >> 1;
    int lh = (tid & 1) * 8;
    const float* aSrc = F + (rowBase + lr) * (size_t)lda + lh;
    const uint4* bSrcH = (const uint4*)(wt_hi + (size_t)(colBase + lr) * lda + lh);
    const uint4* bSrcL = (const uint4*)(wt_lo + (size_t)(colBase + lr) * lda + lh);
    int dstIdx = lr * SROW + (lh >> 1);

    float4 pv0 = ((const float4*)aSrc)[0];
    float4 pv1 = ((const float4*)aSrc)[1];
    uint4 pbh = bSrcH[0], pbl = bSrcL[0];

    for (int kc = 0; kc < nch; kc++) {
        int st = kc & 1;
        {
            float vv[8] = {pv0.x, pv0.y, pv0.z, pv0.w, pv1.x, pv1.y, pv1.z, pv1.w};
            uint32_t hh[4], ll[4];
#pragma unroll
            for (int i = 0; i < 4; i++) {
                float x = vv[2 * i], y = vv[2 * i + 1];
                __nv_bfloat162 hp = __floats2bfloat162_rn(x, y);
                float lx = x - __bfloat162float(hp.x);
                float ly = y - __bfloat162float(hp.y);
                __nv_bfloat162 lp = __floats2bfloat162_rn(lx, ly);
                hh[i] = *(uint32_t*)&hp;
                ll[i] = *(uint32_t*)&lp;
            }
            *(uint4*)&sAh[st][dstIdx] = make_uint4(hh[0], hh[1], hh[2], hh[3]);
            *(uint4*)&sAl[st][dstIdx] = make_uint4(ll[0], ll[1], ll[2], ll[3]);
            *(uint4*)&sBh[st][dstIdx] = pbh;
            *(uint4*)&sBl[st][dstIdx] = pbl;
        }
        __syncthreads();                 // single barrier per chunk
        if (kc + 1 < nch) {
            const float4* s = (const float4*)(aSrc + (kc + 1) * 16);
            pv0 = s[0]; pv1 = s[1];
            pbh = bSrcH[(kc + 1) * 2];
            pbl = bSrcL[(kc + 1) * 2];
        }
        uint32_t soff = st * (STAGE_U32 * 4);   // byte offset into stage 1

        uint32_t aH[2][4], aL[2][4], bH[4][4], bL[4][4];
#pragma unroll
        for (int am = 0; am < 2; am++) {
            ldsm_x4(aH[am], aAH[am] + soff);
            ldsm_x4(aL[am], aAL[am] + soff);
        }
#pragma unroll
        for (int p = 0; p < 4; p++) {
            ldsm_x4(bH[p], bAH[p] + soff);
            ldsm_x4(bL[p], bAL[p] + soff);
        }

#pragma unroll
        for (int am = 0; am < 2; am++) {
#pragma unroll
            for (int p = 0; p < 4; p++) {
                mma_bf16(acc[am][2 * p],     aH[am], &bH[p][0]);
                mma_bf16(acc[am][2 * p],     aL[am], &bH[p][0]);
                mma_bf16(acc[am][2 * p],     aH[am], &bL[p][0]);
                mma_bf16(acc[am][2 * p + 1], aH[am], &bH[p][2]);
                mma_bf16(acc[am][2 * p + 1], aL[am], &bH[p][2]);
                mma_bf16(acc[am][2 * p + 1], aH[am], &bL[p][2]);
            }
        }
    }

    // ---- fused LSTM epilogue ----
    int evenp = (lane & 1) == 0;
#pragma unroll
    for (int am = 0; am < 2; am++) {
#pragma unroll
        for (int rp = 0; rp < 2; rp++) {
            size_t row = rowBase + warpM * 32 + am * 16 + rp * 8 + (lane >> 2);
#pragma unroll
            for (int bn = 0; bn < 8; bn++) {
                int cbase = colBase + warpN * 64 + bn * 8 + (lane & 3) * 2;
                int h = cbase >> 2;
                float a0 = acc[am][bn][rp * 2 + 0];
                float a1 = acc[am][bn][rp * 2 + 1];
                float v0, v1;
                if (evenp) {
                    v0 = sigmoidf_(a0 + __ldg(bias + h));          // i
                    v1 = sigmoidf_(a1 + __ldg(bias + 128 + h));    // f
                } else {
                    v0 = sigmoidf_(a0 + __ldg(bias + 256 + h));    // o
                    v1 = tanhf(a1 + __ldg(bias + 384 + h));        // g
                }
                float ex = __shfl_xor_sync(0xffffffffu, v1, 1);
                float tn = 0.f;
                if (evenp) {
                    float cin = c_in[row * H_ + h];
                    float cn = v1 * cin + v0 * ex;                 // f*c + i*g
                    c_out[row * H_ + h] = cn;
                    tn = tanhf(cn);
                }
                float t2 = __shfl_xor_sync(0xffffffffu, tn, 1);
                if (!evenp) {
                    float hv = v0 * t2;                            // o*tanh(cn)
                    h_out[row * H_ + h] = hv;
                    if (layer == 0)
                        g_feats2[row * (size_t)K1_LDA + h] = hv;
                }
            }
        }
    }
}

// ---------------- mma attention energy + dpw (double-buffered) -------------
__global__ __launch_bounds__(256) void energy_mma_kernel(
    const float* __restrict__ enc, const float* __restrict__ attn_b,
    const float* __restrict__ proj_w, const float* __restrict__ hout) {
    __shared__ __align__(16) uint32_t sAh[2][STAGE_U32];
    __shared__ __align__(16) uint32_t sAl[2][STAGE_U32];
    __shared__ __align__(16) uint32_t sBh[2][STAGE_U32];
    __shared__ __align__(16) uint32_t sBl[2][STAGE_U32];

    int tid = threadIdx.x, lane = tid & 31, wid = tid >> 5;
    int warpM = wid & 3, warpN = wid >> 2;
    size_t tileBase = (size_t)blockIdx.x * 128;

    uint32_t aAH[2], aAL[2], bAH[4], bAL[4];
#pragma unroll
    for (int am = 0; am < 2; am++) {
        int r = warpM * 32 + am * 16 + (lane & 15);
        int c = (lane >> 4) * 4;
        aAH[am] = smem_u32(&sAh[0][r * SROW + c]);
        aAL[am] = smem_u32(&sAl[0][r * SROW + c]);
    }
#pragma unroll
    for (int p = 0; p < 4; p++) {
        int quad = lane >> 3;
        int rowo = ((quad == 0 || quad == 1) ? 0 : 8) + (lane & 7);
        int c = (quad & 1) * 4;
        int n = warpN * 64 + p * 16 + rowo;
        bAH[p] = smem_u32(&sBh[0][n * SROW + c]);
        bAL[p] = smem_u32(&sBl[0][n * SROW + c]);
    }

    float acc[2][8][4];
#pragma unroll
    for (int i = 0; i < 2; i++)
#pragma unroll
        for (int j = 0; j < 8; j++)
#pragma unroll
            for (int q = 0; q < 4; q++) acc[i][j][q] = 0.f;

    int lr = tid >> 1;
    int lh = (tid & 1) * 8;
    const float* aSrc = enc + (tileBase + lr) * (size_t)H_ + lh;
    const uint4* bSrcH = (const uint4*)(g_awh + (size_t)lr * 128 + lh);
    const uint4* bSrcL = (const uint4*)(g_awl + (size_t)lr * 128 + lh);
    int dstIdx = lr * SROW + (lh >> 1);

    float dpw = 0.f;

    float4 pv0 = ((const float4*)aSrc)[0];
    float4 pv1 = ((const float4*)aSrc)[1];
    uint4 pbh = bSrcH[0], pbl = bSrcL[0];

    const int nch = H_ / 16;  // 8
    for (int kc = 0; kc < nch; kc++) {
        int st = kc & 1;
        {
            float vv[8] = {pv0.x, pv0.y, pv0.z, pv0.w, pv1.x, pv1.y, pv1.z, pv1.w};
            const float4* pwp = (const float4*)(proj_w + 128 + kc * 16 + lh);
            float4 w0 = __ldg(pwp), w1 = __ldg(pwp + 1);
            dpw += vv[0] * w0.x + vv[1] * w0.y + vv[2] * w0.z + vv[3] * w0.w
                 + vv[4] * w1.x + vv[5] * w1.y + vv[6] * w1.z + vv[7] * w1.w;
            uint32_t hh[4], ll[4];
#pragma unroll
            for (int i = 0; i < 4; i++) {
                float x = vv[2 * i], y = vv[2 * i + 1];
                __nv_bfloat162 hp = __floats2bfloat162_rn(x, y);
                float lx = x - __bfloat162float(hp.x);
                float ly = y - __bfloat162float(hp.y);
                __nv_bfloat162 lp = __floats2bfloat162_rn(lx, ly);
                hh[i] = *(uint32_t*)&hp;
                ll[i] = *(uint32_t*)&lp;
            }
            *(uint4*)&sAh[st][dstIdx] = make_uint4(hh[0], hh[1], hh[2], hh[3]);
            *(uint4*)&sAl[st][dstIdx] = make_uint4(ll[0], ll[1], ll[2], ll[3]);
            *(uint4*)&sBh[st][dstIdx] = pbh;
            *(uint4*)&sBl[st][dstIdx] = pbl;
        }
        __syncthreads();
        if (kc + 1 < nch) {
            const float4* s = (const float4*)(aSrc + (kc + 1) * 16);
            pv0 = s[0]; pv1 = s[1];
            pbh = bSrcH[(kc + 1) * 2];
            pbl = bSrcL[(kc + 1) * 2];
        }
        uint32_t soff = st * (STAGE_U32 * 4);

        uint32_t aH[2][4], aL[2][4], bH[4][4], bL[4][4];
#pragma unroll
        for (int am = 0; am < 2; am++) {
            ldsm_x4(aH[am], aAH[am] + soff);
            ldsm_x4(aL[am], aAL[am] + soff);
        }
#pragma unroll
        for (int p = 0; p < 4; p++) {
            ldsm_x4(bH[p], bAH[p] + soff);
            ldsm_x4(bL[p], bAL[p] + soff);
        }

#pragma unroll
        for (int am = 0; am < 2; am++) {
#pragma unroll
            for (int p = 0; p < 4; p++) {
                mma_bf16(acc[am][2 * p],     aH[am], &bH[p][0]);
                mma_bf16(acc[am][2 * p],     aL[am], &bH[p][0]);
                mma_bf16(acc[am][2 * p],     aH[am], &bL[p][0]);
                mma_bf16(acc[am][2 * p + 1], aH[am], &bH[p][2]);
                mma_bf16(acc[am][2 * p + 1], aL[am], &bH[p][2]);
                mma_bf16(acc[am][2 * p + 1], aH[am], &bL[p][2]);
            }
        }
    }

    {
        float d2 = dpw + __shfl_xor_sync(0xffffffffu, dpw, 1);
        if ((tid & 1) == 0) g_dpw[tileBase + lr] = d2;
    }

    // epilogue: tanh(+b) * hout, reduce over 128 cols.
    // scratch aliases stage-0 sAh (dead after final barrier of the loop).
    float* sred = (float*)&sAh[0][0];   // [warpM][am][rp][8]
    float ev[2][2] = {{0.f, 0.f}, {0.f, 0.f}};
#pragma unroll
    for (int am = 0; am < 2; am++) {
        size_t gr0 = tileBase + warpM * 32 + am * 16 + (lane >> 2);
        size_t gr1 = gr0 + 8;
        const float* h0p = hout + (size_t)(gr0 & (BN - 1)) * H_;
        const float* h1p = hout + (size_t)(gr1 & (BN - 1)) * H_;
#pragma unroll
        for (int bn = 0; bn < 8; bn++) {
            int col = warpN * 64 + bn * 8 + (lane & 3) * 2;
            float2 bb = *(const float2*)(attn_b + col);
            float2 h0 = *(const float2*)(h0p + col);
            float2 h1 = *(const float2*)(h1p + col);
            ev[am][0] += tanhf(acc[am][bn][0] + bb.x) * h0.x
                       + tanhf(acc[am][bn][1] + bb.y) * h0.y;
            ev[am][1] += tanhf(acc[am][bn][2] + bb.x) * h1.x
                       + tanhf(acc[am][bn][3] + bb.y) * h1.y;
        }
    }
#pragma unroll
    for (int am = 0; am < 2; am++)
#pragma unroll
        for (int rp = 0; rp < 2; rp++) {
            ev[am][rp] += __shfl_xor_sync(0xffffffffu, ev[am][rp], 1);
            ev[am][rp] += __shfl_xor_sync(0xffffffffu, ev[am][rp], 2);
        }
    if (warpN == 1 && (lane & 3) == 0) {
#pragma unroll
        for (int am = 0; am < 2; am++)
#pragma unroll
            for (int rp = 0; rp < 2; rp++)
                sred[((warpM * 2 + am) * 2 + rp) * 8 + (lane >> 2)] = ev[am][rp];
    }
    __syncthreads();
    if (warpN == 0 && (lane & 3) == 0) {
#pragma unroll
        for (int am = 0; am < 2; am++)
#pragma unroll
            for (int rp = 0; rp < 2; rp++) {
                size_t gr = tileBase + warpM * 32 + am * 16 + rp * 8 + (lane >> 2);
                g_energy[gr] = ev[am][rp]
                    + sred[((warpM * 2 + am) * 2 + rp) * 8 + (lane >> 2)];
            }
    }
}

// ---------------- softmax over S + attw + final projection -----------------
__global__ void softmax_out_kernel(const float* __restrict__ proj_w,
                                   const float* __restrict__ proj_b,
                                   const float* __restrict__ hout,
                                   float* __restrict__ out0,
                                   float* __restrict__ attw) {
    int gwarp = (blockIdx.x * blockDim.x + threadIdx.x) >> 5;
    int lane = threadIdx.x & 31;
    if (gwarp >= BN) return;
    int bn = gwarp;

    float e = (lane < S_) ? g_energy[lane * BN + bn] : -1e30f;
    float m = e;
#pragma unroll
    for (int off = 16; off > 0; off >>= 1)
        m = fmaxf(m, __shfl_xor_sync(0xffffffffu, m, off));
    float p = (lane < S_) ? expf(e - m) : 0.f;
    float s = p;
#pragma unroll
    for (int off = 16; off > 0; off >>= 1)
        s += __shfl_xor_sync(0xffffffffu, s, off);
    float a = p / s;
    if (lane < S_) attw[(size_t)bn * S_ + lane] = a;

    float acc = (lane < S_) ? a * g_dpw[lane * BN + bn] : 0.f;
#pragma unroll
    for (int j = 0; j < 4; j++) {
        int col = lane + j * 32;
        acc += hout[(size_t)bn * H_ + col] * proj_w[col];
    }
#pragma unroll
    for (int off = 16; off > 0; off >>= 1)
        acc += __shfl_xor_sync(0xffffffffu, acc, off);
    if (lane == 0) out0[bn] = acc + proj_b[0];
}

// ---------------- orchestration: kernel launches ONLY ----------------------
extern "C" void kernel_launch(void* const* d_in, const int* in_sizes, int n_in,
                              void* d_out, int out_size) {
    const float* inputs  = (const float*)d_in[0];
    const float* enc     = (const float*)d_in[1];
    const float* hidden  = (const float*)d_in[2];
    const float* cell    = (const float*)d_in[3];
    const float* sup     = (const float*)d_in[4];
    const float* w0      = (const float*)d_in[5];
    const float* b0      = (const float*)d_in[6];
    const float* w1      = (const float*)d_in[7];
    const float* b1      = (const float*)d_in[8];
    const float* attn_w  = (const float*)d_in[9];
    const float* attn_b  = (const float*)d_in[10];
    const float* proj_w  = (const float*)d_in[11];
    const float* proj_b  = (const float*)d_in[12];
    float* out = (float*)d_out;

    float* hs0 = out + HS_OFF;
    float* hs1 = out + HS_OFF + (size_t)BN * H_;
    float* cs0 = out + CS_OFF;
    float* cs1 = out + CS_OFF + (size_t)BN * H_;
    float* attw = out + ATT_OFF;

    // launch index 3 = gates_mma layer0 (ncu samples index 3)
    setup_kernel<<<19264, 256>>>(inputs, hidden, hidden + (size_t)BN * H_,
                                 sup, w0, w1, attn_w);                        // 0
    spmmv_kernel<<<dim3(N_, B_ / 4), 128>>>(0, K0_LDA, 0, 132, -1, 132, 0);   // 1
    spmmv_kernel<<<dim3(N_, B_ / 4), 128>>>(0, K0_LDA, 132, 264, 0, 132, 1);  // 2
    gates_mma_kernel<<<dim3(4, BN / 128), 256>>>(b0, cell, hs0, cs0,
                                                 K0_LDA, K0_LDA / 16, 0);     // 3
    spmmv_kernel<<<dim3(N_, B_ / 4), 128>>>(1, K1_LDA, 0, 256, -1, 256, 0);   // 4
    spmmv_kernel<<<dim3(N_, B_ / 4), 128>>>(1, K1_LDA, 256, 512, 0, 256, 1);  // 5
    gates_mma_kernel<<<dim3(4, BN / 128), 256>>>(b1, cell + (size_t)BN * H_,
                                                 hs1, cs1,
                                                 K1_LDA, K1_LDA / 16, 1);     // 6
    energy_mma_kernel<<<(S_ * BN) / 128, 256>>>(enc, attn_b, proj_w, hs1);    // 7
    softmax_out_kernel<<<BN / 8, 256>>>(proj_w, proj_b, hs1, out, attw);      // 8
}